// round 2
// baseline (speedup 1.0000x reference)
#include <cuda_runtime.h>
#include <cstdint>

typedef unsigned long long ull;

#define ROWS_TOT 40000
#define ROWS_SF  20000

// ---------------- scratch (static device globals; no allocations) ----------------
__device__ float g_psum[8 * 1024];
__device__ float g_cnt[8];
__device__ float g_pvec[8 * 1024];          // P[:,idx_b] * 32 * sign_b / ||P[:,idx_b]||
__device__ float g_a[ROWS_TOT];             // per-row enhancement scalar (1+g)
__device__ float g_h[(size_t)ROWS_TOT * 64];// hidden activations

// ---------------- packed f32x2 helpers ----------------
__device__ __forceinline__ ull pk2(float x, float y) {
    ull r; asm("mov.b64 %0, {%1,%2};" : "=l"(r) : "f"(x), "f"(y)); return r;
}
__device__ __forceinline__ void fma2(ull &d, ull a, ull b) {
    asm("fma.rn.f32x2 %0, %1, %2, %0;" : "+l"(d) : "l"(a), "l"(b));
}
__device__ __forceinline__ float2 upk2(ull v) {
    float2 r; asm("mov.b64 {%0,%1}, %2;" : "=f"(r.x), "=f"(r.y) : "l"(v)); return r;
}

// ---------------- K0: zero accumulators ----------------
__global__ void zero_k() {
    int i = blockIdx.x * 256 + threadIdx.x;
    if (i < 8192) g_psum[i] = 0.0f;
    if (i < 8)    g_cnt[i]  = 0.0f;
}

// ---------------- K1: masked prototype sum ----------------
// grid (20, 8): blockIdx.y = batch, blockIdx.x = 125-row chunk. 256 thr, thread owns 4 cols.
__global__ void proto_sum_k(const float* __restrict__ s_f, const float* __restrict__ s_y) {
    const int b  = blockIdx.y;
    const int n0 = blockIdx.x * 125;
    const int t  = threadIdx.x;
    const float* sy = s_y + (size_t)b * 160000;   // [400,400], S=1
    float4 acc = make_float4(0.f, 0.f, 0.f, 0.f);
    int cnt = 0;
    for (int n = n0; n < n0 + 125; n++) {
        // nearest-neighbor downsample: mask(i,j) = s_y[8i, 8j] == 1
        float m = sy[(n / 50) * 3200 + (n % 50) * 8];
        if (m == 1.0f) {
            float4 v = *(const float4*)(s_f + (size_t)(b * 2500 + n) * 1024 + t * 4);
            acc.x += v.x; acc.y += v.y; acc.z += v.z; acc.w += v.w;
            cnt++;
        }
    }
    float* ps = g_psum + b * 1024 + t * 4;
    atomicAdd(ps + 0, acc.x); atomicAdd(ps + 1, acc.y);
    atomicAdd(ps + 2, acc.z); atomicAdd(ps + 3, acc.w);
    if (t == 0) atomicAdd(&g_cnt[b], (float)cnt);
}

// ---------------- K2: prototype selection (1 CTA, 256 threads) ----------------
__global__ void select_k(const float* __restrict__ P) {   // P: [1024,16] row-major (d*16+c)
    __shared__ float norm2[16];
    __shared__ float sims[8][16];
    __shared__ int   sel[8];
    __shared__ float fac[8];
    const int t = threadIdx.x, lane = t & 31, w = t >> 5;

    for (int c = w; c < 16; c += 8) {
        float s = 0.f;
        for (int d = lane; d < 1024; d += 32) { float v = P[d * 16 + c]; s += v * v; }
        #pragma unroll
        for (int o = 16; o; o >>= 1) s += __shfl_xor_sync(0xFFFFFFFFu, s, o);
        if (!lane) norm2[c] = s;
    }
    __syncthreads();
    for (int p = w; p < 128; p += 8) {
        int b = p >> 4, c = p & 15;
        const float* ps = g_psum + b * 1024;
        float s = 0.f;
        for (int d = lane; d < 1024; d += 32) s += ps[d] * P[d * 16 + c];
        #pragma unroll
        for (int o = 16; o; o >>= 1) s += __shfl_xor_sync(0xFFFFFFFFu, s, o);
        if (!lane) sims[b][c] = s * rsqrtf(fmaxf(norm2[c], 1e-24f));
    }
    __syncthreads();
    if (t < 8) {
        int best = 0; float bv = sims[t][0];
        #pragma unroll
        for (int c = 1; c < 16; c++) if (sims[t][c] > bv) { bv = sims[t][c]; best = c; }
        sel[t] = best;
        float sign = (g_cnt[t] > 0.5f) ? 1.0f : 0.0f;           // count is 0 or >=1
        fac[t] = sign * 32.0f * rsqrtf(fmaxf(norm2[best], 1e-24f)); // 32 = sqrt(1024)
    }
    __syncthreads();
    for (int e = t; e < 8192; e += 256) {
        int b = e >> 10, d = e & 1023;
        g_pvec[e] = P[d * 16 + sel[b]] * fac[b];
    }
}

// ---------------- K3: per-row enhancement scalar ----------------
// grid 5000, 256 thr = 8 warps; warp per row.
__global__ void row_a_k(const float* __restrict__ x, const float* __restrict__ s_f) {
    const int r = blockIdx.x * 8 + (threadIdx.x >> 5);
    const int lane = threadIdx.x & 31;
    const float* src;
    int b;
    if (r < ROWS_SF) { src = s_f + (size_t)r * 1024;              b = r / 2500; }
    else             { src = x + (size_t)(r - ROWS_SF) * 1024;    b = (r - ROWS_SF) / 2500; }
    const float* pv = g_pvec + b * 1024;
    float sq = 0.f, dp = 0.f;
    #pragma unroll
    for (int i = 0; i < 8; i++) {
        int c = lane * 4 + i * 128;
        float4 f = *(const float4*)(src + c);
        float4 p = *(const float4*)(pv + c);
        sq = fmaf(f.x, f.x, fmaf(f.y, f.y, fmaf(f.z, f.z, fmaf(f.w, f.w, sq))));
        dp = fmaf(f.x, p.x, fmaf(f.y, p.y, fmaf(f.z, p.z, fmaf(f.w, p.w, dp))));
    }
    #pragma unroll
    for (int o = 16; o; o >>= 1) {
        sq += __shfl_xor_sync(0xFFFFFFFFu, sq, o);
        dp += __shfl_xor_sync(0xFFFFFFFFu, dp, o);
    }
    if (!lane) {
        float g = fminf(fmaxf(dp / fmaxf(sqrtf(sq), 1e-12f), 0.0f), 6.0f);  // ReLU6
        g_a[r] = 1.0f + g;
    }
}

// ---------------- K4: down GEMM  H = relu(a*(F @ Wd^T) + b_down) ----------------
// BM=144, BN=64, BK=32, 288 threads (18x16). Thread: rows ty*8..+7 (4 f32x2 pairs), cols tx*4..+3.
#define D_ASTR 146
#define D_BSTR 68
__global__ void __launch_bounds__(288, 2) down_gemm_k(
    const float* __restrict__ x, const float* __restrict__ s_f,
    const float* __restrict__ Wd, const float* __restrict__ bdn) {
    __shared__ __align__(16) float As[32 * D_ASTR];
    __shared__ __align__(16) float Bs[32 * D_BSTR];
    const int t = threadIdx.x;
    const int tx = t & 15, ty = t >> 4;
    const int row0 = blockIdx.x * 144;

    ull acc[4][4];
    #pragma unroll
    for (int j = 0; j < 4; j++)
        #pragma unroll
        for (int n = 0; n < 4; n++) acc[j][n] = 0ull;

    for (int k0 = 0; k0 < 1024; k0 += 32) {
        // A tile: 144 rows x 32 k, k-major in smem, 4 float4 loads/thread
        #pragma unroll
        for (int i = 0; i < 4; i++) {
            int idx = t + i * 288;
            int r = idx >> 3, c4 = (idx & 7) << 2;
            int row = row0 + r;
            float4 v = make_float4(0.f, 0.f, 0.f, 0.f);
            if (row < ROWS_TOT) {
                const float* src = (row < ROWS_SF) ? (s_f + (size_t)row * 1024)
                                                   : (x + (size_t)(row - ROWS_SF) * 1024);
                v = *(const float4*)(src + k0 + c4);
            }
            As[(c4 + 0) * D_ASTR + r] = v.x;
            As[(c4 + 1) * D_ASTR + r] = v.y;
            As[(c4 + 2) * D_ASTR + r] = v.z;
            As[(c4 + 3) * D_ASTR + r] = v.w;
        }
        // B tile: Bs[k][j] = Wd[j][k0+k]; 64 j x 32 k = 512 float4
        #pragma unroll
        for (int i = 0; i < 2; i++) {
            int idx = t + i * 288;
            if (idx < 512) {
                int j = idx >> 3, c4 = (idx & 7) << 2;
                float4 v = *(const float4*)(Wd + (size_t)j * 1024 + k0 + c4);
                Bs[(c4 + 0) * D_BSTR + j] = v.x;
                Bs[(c4 + 1) * D_BSTR + j] = v.y;
                Bs[(c4 + 2) * D_BSTR + j] = v.z;
                Bs[(c4 + 3) * D_BSTR + j] = v.w;
            }
        }
        __syncthreads();
        #pragma unroll
        for (int k = 0; k < 32; k++) {
            const float* ar = &As[k * D_ASTR + ty * 8];
            ull a0 = *(const ull*)(ar + 0);
            ull a1 = *(const ull*)(ar + 2);
            ull a2 = *(const ull*)(ar + 4);
            ull a3 = *(const ull*)(ar + 6);
            float4 bq = *(const float4*)&Bs[k * D_BSTR + tx * 4];
            ull b0 = pk2(bq.x, bq.x), b1 = pk2(bq.y, bq.y);
            ull b2 = pk2(bq.z, bq.z), b3 = pk2(bq.w, bq.w);
            fma2(acc[0][0], a0, b0); fma2(acc[0][1], a0, b1); fma2(acc[0][2], a0, b2); fma2(acc[0][3], a0, b3);
            fma2(acc[1][0], a1, b0); fma2(acc[1][1], a1, b1); fma2(acc[1][2], a1, b2); fma2(acc[1][3], a1, b3);
            fma2(acc[2][0], a2, b0); fma2(acc[2][1], a2, b1); fma2(acc[2][2], a2, b2); fma2(acc[2][3], a2, b3);
            fma2(acc[3][0], a3, b0); fma2(acc[3][1], a3, b1); fma2(acc[3][2], a3, b2); fma2(acc[3][3], a3, b3);
        }
        __syncthreads();
    }
    // epilogue: h = relu(a*dot + b_down)
    float4 bd4 = *(const float4*)(bdn + tx * 4);
    #pragma unroll
    for (int j = 0; j < 4; j++) {
        float2 c0 = upk2(acc[j][0]), c1 = upk2(acc[j][1]);
        float2 c2 = upk2(acc[j][2]), c3 = upk2(acc[j][3]);
        int row = row0 + ty * 8 + 2 * j;
        if (row < ROWS_TOT) {
            float av = g_a[row];
            float4 o;
            o.x = fmaxf(fmaf(av, c0.x, bd4.x), 0.f);
            o.y = fmaxf(fmaf(av, c1.x, bd4.y), 0.f);
            o.z = fmaxf(fmaf(av, c2.x, bd4.z), 0.f);
            o.w = fmaxf(fmaf(av, c3.x, bd4.w), 0.f);
            *(float4*)&g_h[(size_t)row * 64 + tx * 4] = o;
        }
        if (row + 1 < ROWS_TOT) {
            float av = g_a[row + 1];
            float4 o;
            o.x = fmaxf(fmaf(av, c0.y, bd4.x), 0.f);
            o.y = fmaxf(fmaf(av, c1.y, bd4.y), 0.f);
            o.z = fmaxf(fmaf(av, c2.y, bd4.z), 0.f);
            o.w = fmaxf(fmaf(av, c3.y, bd4.w), 0.f);
            *(float4*)&g_h[(size_t)(row + 1) * 64 + tx * 4] = o;
        }
    }
}

// ---------------- K5: up GEMM  out = H @ Wu^T + b_up ----------------
// BM=128, BN=128, BK=32 (K=64 total), 256 threads (16x16).
// Thread: rows ty*8..+7 (4 pairs), cols tx*8..+7.
#define U_ASTR 130
#define U_BSTR 132
__global__ void __launch_bounds__(256, 2) up_gemm_k(
    const float* __restrict__ Wu, const float* __restrict__ bup, float* __restrict__ out) {
    __shared__ __align__(16) float As[32 * U_ASTR];
    __shared__ __align__(16) float Bs[32 * U_BSTR];
    const int t = threadIdx.x;
    const int tx = t & 15, ty = t >> 4;
    const int row0 = blockIdx.x * 128;
    const int nblk = blockIdx.y * 128;

    ull acc[4][8];
    #pragma unroll
    for (int j = 0; j < 4; j++)
        #pragma unroll
        for (int n = 0; n < 8; n++) acc[j][n] = 0ull;

    for (int k0 = 0; k0 < 64; k0 += 32) {
        // A tile from g_h: 128 rows x 32 k
        #pragma unroll
        for (int i = 0; i < 4; i++) {
            int idx = t + i * 256;
            int r = idx >> 3, c4 = (idx & 7) << 2;
            int row = row0 + r;
            float4 v = make_float4(0.f, 0.f, 0.f, 0.f);
            if (row < ROWS_TOT) v = *(const float4*)(g_h + (size_t)row * 64 + k0 + c4);
            As[(c4 + 0) * U_ASTR + r] = v.x;
            As[(c4 + 1) * U_ASTR + r] = v.y;
            As[(c4 + 2) * U_ASTR + r] = v.z;
            As[(c4 + 3) * U_ASTR + r] = v.w;
        }
        // B tile: Bs[k][n] = Wu[nblk+n][k0+k]; 128 n x 32 k
        #pragma unroll
        for (int i = 0; i < 4; i++) {
            int idx = t + i * 256;
            int n = idx >> 3, c4 = (idx & 7) << 2;
            float4 v = *(const float4*)(Wu + (size_t)(nblk + n) * 64 + k0 + c4);
            Bs[(c4 + 0) * U_BSTR + n] = v.x;
            Bs[(c4 + 1) * U_BSTR + n] = v.y;
            Bs[(c4 + 2) * U_BSTR + n] = v.z;
            Bs[(c4 + 3) * U_BSTR + n] = v.w;
        }
        __syncthreads();
        #pragma unroll
        for (int k = 0; k < 32; k++) {
            const float* ar = &As[k * U_ASTR + ty * 8];
            ull a0 = *(const ull*)(ar + 0);
            ull a1 = *(const ull*)(ar + 2);
            ull a2 = *(const ull*)(ar + 4);
            ull a3 = *(const ull*)(ar + 6);
            float4 q0 = *(const float4*)&Bs[k * U_BSTR + tx * 8];
            float4 q1 = *(const float4*)&Bs[k * U_BSTR + tx * 8 + 4];
            ull b0 = pk2(q0.x, q0.x), b1 = pk2(q0.y, q0.y), b2 = pk2(q0.z, q0.z), b3 = pk2(q0.w, q0.w);
            ull b4 = pk2(q1.x, q1.x), b5 = pk2(q1.y, q1.y), b6 = pk2(q1.z, q1.z), b7 = pk2(q1.w, q1.w);
            #pragma unroll
            for (int j = 0; j < 4; j++) {
                ull aj = (j == 0) ? a0 : (j == 1) ? a1 : (j == 2) ? a2 : a3;
                fma2(acc[j][0], aj, b0); fma2(acc[j][1], aj, b1);
                fma2(acc[j][2], aj, b2); fma2(acc[j][3], aj, b3);
                fma2(acc[j][4], aj, b4); fma2(acc[j][5], aj, b5);
                fma2(acc[j][6], aj, b6); fma2(acc[j][7], aj, b7);
            }
        }
        __syncthreads();
    }
    // epilogue: + b_up
    float4 u0 = *(const float4*)(bup + nblk + tx * 8);
    float4 u1 = *(const float4*)(bup + nblk + tx * 8 + 4);
    #pragma unroll
    for (int j = 0; j < 4; j++) {
        float2 c0 = upk2(acc[j][0]), c1 = upk2(acc[j][1]), c2 = upk2(acc[j][2]), c3 = upk2(acc[j][3]);
        float2 c4_ = upk2(acc[j][4]), c5 = upk2(acc[j][5]), c6 = upk2(acc[j][6]), c7 = upk2(acc[j][7]);
        int row = row0 + ty * 8 + 2 * j;
        if (row < ROWS_TOT) {
            float* dst = out + (size_t)row * 1024 + nblk + tx * 8;
            float4 o0 = make_float4(c0.x + u0.x, c1.x + u0.y, c2.x + u0.z, c3.x + u0.w);
            float4 o1 = make_float4(c4_.x + u1.x, c5.x + u1.y, c6.x + u1.z, c7.x + u1.w);
            *(float4*)dst = o0; *(float4*)(dst + 4) = o1;
        }
        if (row + 1 < ROWS_TOT) {
            float* dst = out + (size_t)(row + 1) * 1024 + nblk + tx * 8;
            float4 o0 = make_float4(c0.y + u0.x, c1.y + u0.y, c2.y + u0.z, c3.y + u0.w);
            float4 o1 = make_float4(c4_.y + u1.x, c5.y + u1.y, c6.y + u1.z, c7.y + u1.w);
            *(float4*)dst = o0; *(float4*)(dst + 4) = o1;
        }
    }
}

// ---------------- launch ----------------
extern "C" void kernel_launch(void* const* d_in, const int* in_sizes, int n_in,
                              void* d_out, int out_size) {
    (void)in_sizes; (void)n_in; (void)out_size;
    const float* x   = (const float*)d_in[0];
    const float* s_f = (const float*)d_in[1];
    const float* s_y = (const float*)d_in[2];
    const float* P   = (const float*)d_in[3];
    const float* Wd  = (const float*)d_in[4];
    const float* bd  = (const float*)d_in[5];
    const float* Wu  = (const float*)d_in[6];
    const float* bu  = (const float*)d_in[7];
    float* out = (float*)d_out;

    zero_k<<<32, 256>>>();
    proto_sum_k<<<dim3(20, 8), 256>>>(s_f, s_y);
    select_k<<<1, 256>>>(P);
    row_a_k<<<5000, 256>>>(x, s_f);
    down_gemm_k<<<278, 288>>>(x, s_f, Wd, bd);
    up_gemm_k<<<dim3(313, 8), 256>>>(Wu, bu, out);
}

// round 4
// speedup vs baseline: 1.2760x; 1.2760x over previous
#include <cuda_runtime.h>
#include <cuda_bf16.h>
#include <cstdint>

#define ROWS_TOT 40000
#define ROWS_SF  20000
#define AP 36            // smem row stride in 32-bit words (= 72 bf16, conflict-free)

// ---------------- scratch (static device globals; no runtime allocation) ----------------
__device__ float g_psum[8 * 1024];
__device__ float g_cnt[8];
__device__ float g_pvec[8 * 1024];
__device__ __align__(16) __nv_bfloat16 g_wd_hi[64 * 1024];
__device__ __align__(16) __nv_bfloat16 g_wd_lo[64 * 1024];
__device__ __align__(16) __nv_bfloat16 g_wu_hi[1024 * 64];
__device__ __align__(16) __nv_bfloat16 g_wu_lo[1024 * 64];
__device__ __align__(16) __nv_bfloat16 g_h_hi[(size_t)ROWS_TOT * 64];
__device__ __align__(16) __nv_bfloat16 g_h_lo[(size_t)ROWS_TOT * 64];

// ---------------- helpers ----------------
__device__ __forceinline__ void mma_bf16(float* d, uint32_t a0, uint32_t a1, uint32_t a2,
                                         uint32_t a3, uint32_t b0, uint32_t b1) {
    asm volatile(
        "mma.sync.aligned.m16n8k16.row.col.f32.bf16.bf16.f32 "
        "{%0,%1,%2,%3}, {%4,%5,%6,%7}, {%8,%9}, {%0,%1,%2,%3};"
        : "+f"(d[0]), "+f"(d[1]), "+f"(d[2]), "+f"(d[3])
        : "r"(a0), "r"(a1), "r"(a2), "r"(a3), "r"(b0), "r"(b1));
}
__device__ __forceinline__ uint32_t pack_hi2(float x, float y) {
    __nv_bfloat162 h = __float22bfloat162_rn(make_float2(x, y));
    return *reinterpret_cast<uint32_t*>(&h);
}
__device__ __forceinline__ float2 unhi2(uint32_t u) {
    __nv_bfloat162 h = *reinterpret_cast<__nv_bfloat162*>(&u);
    return make_float2(__low2float(h), __high2float(h));
}

// ---------------- K0: zero accumulators ----------------
__global__ void zero_k() {
    int i = blockIdx.x * 256 + threadIdx.x;
    if (i < 8192) g_psum[i] = 0.0f;
    if (i < 8)    g_cnt[i]  = 0.0f;
}

// ---------------- K1: masked prototype sum ----------------
__global__ void proto_sum_k(const float* __restrict__ s_f, const float* __restrict__ s_y) {
    const int b  = blockIdx.y;
    const int n0 = blockIdx.x * 125;
    const int t  = threadIdx.x;
    const float* sy = s_y + (size_t)b * 160000;
    float4 acc = make_float4(0.f, 0.f, 0.f, 0.f);
    int cnt = 0;
    for (int n = n0; n < n0 + 125; n++) {
        float m = sy[(n / 50) * 3200 + (n % 50) * 8];   // nearest-neighbor stride-8
        if (m == 1.0f) {
            float4 v = *(const float4*)(s_f + (size_t)(b * 2500 + n) * 1024 + t * 4);
            acc.x += v.x; acc.y += v.y; acc.z += v.z; acc.w += v.w;
            cnt++;
        }
    }
    float* ps = g_psum + b * 1024 + t * 4;
    atomicAdd(ps + 0, acc.x); atomicAdd(ps + 1, acc.y);
    atomicAdd(ps + 2, acc.z); atomicAdd(ps + 3, acc.w);
    if (t == 0) atomicAdd(&g_cnt[b], (float)cnt);
}

// ---------------- K2: prototype selection ----------------
__global__ void select_k(const float* __restrict__ P) {   // P: [1024,16] row-major
    __shared__ float norm2[16];
    __shared__ float sims[8][16];
    __shared__ int   sel[8];
    __shared__ float fac[8];
    const int t = threadIdx.x, lane = t & 31, w = t >> 5;

    for (int c = w; c < 16; c += 8) {
        float s = 0.f;
        for (int d = lane; d < 1024; d += 32) { float v = P[d * 16 + c]; s += v * v; }
        #pragma unroll
        for (int o = 16; o; o >>= 1) s += __shfl_xor_sync(0xFFFFFFFFu, s, o);
        if (!lane) norm2[c] = s;
    }
    __syncthreads();
    for (int p = w; p < 128; p += 8) {
        int b = p >> 4, c = p & 15;
        const float* ps = g_psum + b * 1024;
        float s = 0.f;
        for (int d = lane; d < 1024; d += 32) s += ps[d] * P[d * 16 + c];
        #pragma unroll
        for (int o = 16; o; o >>= 1) s += __shfl_xor_sync(0xFFFFFFFFu, s, o);
        if (!lane) sims[b][c] = s * rsqrtf(fmaxf(norm2[c], 1e-24f));
    }
    __syncthreads();
    if (t < 8) {
        int best = 0; float bv = sims[t][0];
        #pragma unroll
        for (int c = 1; c < 16; c++) if (sims[t][c] > bv) { bv = sims[t][c]; best = c; }
        sel[t] = best;
        float sign = (g_cnt[t] > 0.5f) ? 1.0f : 0.0f;
        fac[t] = sign * 32.0f * rsqrtf(fmaxf(norm2[best], 1e-24f));
    }
    __syncthreads();
    for (int e = t; e < 8192; e += 256) {
        int b = e >> 10, d = e & 1023;
        g_pvec[e] = P[d * 16 + sel[b]] * fac[b];
    }
}

// ---------------- K3: weight prep (bf16 hi/lo) ----------------
__global__ void prep_w_k(const float* __restrict__ Wd, const float* __restrict__ Wu) {
    int i = blockIdx.x * 256 + threadIdx.x;
    if (i < 65536) {                       // Wd [64][1024]
        float v = Wd[i];
        __nv_bfloat16 h = __float2bfloat16_rn(v);
        g_wd_hi[i] = h;
        g_wd_lo[i] = __float2bfloat16_rn(v - __bfloat162float(h));
    } else if (i < 131072) {               // Wu [1024][64]
        i -= 65536;
        float v = Wu[i];
        __nv_bfloat16 h = __float2bfloat16_rn(v);
        g_wu_hi[i] = h;
        g_wu_lo[i] = __float2bfloat16_rn(v - __bfloat162float(h));
    }
}

// ================= K4: down GEMM (fused enhance) =================
// BM=128, BN=64, K=1024 (16 chunks of 64). 256 thr = 8 warps (4 m x 2 n).
// smem words: Ah[0,4608) Al[4608,9216) Bh[9216,11520) Bl[11520,13824) a[13824,13952)
extern __shared__ uint32_t smw[];

__global__ void __launch_bounds__(256, 2)
down_k(const float* __restrict__ x, const float* __restrict__ s_f,
       const float* __restrict__ bdn) {
    uint32_t* Ah = smw;
    uint32_t* Al = smw + 4608;
    uint32_t* Bh = smw + 9216;
    uint32_t* Bl = smw + 11520;
    float*    sA = (float*)(smw + 13824);

    const int t = threadIdx.x, wid = t >> 5, lane = t & 31;
    const int warpM = wid & 3, warpN = wid >> 2;
    const int row0 = blockIdx.x * 128;
    const int rl = t >> 1, half = t & 1;
    const int grow = row0 + rl;
    const bool rok = grow < ROWS_TOT;
    const float* src = rok ? ((grow < ROWS_SF) ? s_f + (size_t)grow * 1024
                                               : x + (size_t)(grow - ROWS_SF) * 1024)
                           : x;
    const int bb = rok ? ((grow < ROWS_SF) ? grow / 2500 : (grow - ROWS_SF) / 2500) : 0;
    const float* pvp = g_pvec + bb * 1024 + half * 32;

    float acc[8][4];
    #pragma unroll
    for (int i = 0; i < 8; i++)
        #pragma unroll
        for (int j = 0; j < 4; j++) acc[i][j] = 0.f;

    float sq = 0.f, dp = 0.f;

    for (int c = 0; c < 16; c++) {
        const int kb = c * 64 + half * 32;
        // stage A fp32 -> regs, accumulate sq/dp
        float4 f[8];
        #pragma unroll
        for (int i = 0; i < 8; i++) {
            f[i] = rok ? *(const float4*)(src + kb + i * 4) : make_float4(0.f, 0.f, 0.f, 0.f);
            float4 p = *(const float4*)(pvp + c * 64 + i * 4);
            sq = fmaf(f[i].x, f[i].x, fmaf(f[i].y, f[i].y, fmaf(f[i].z, f[i].z, fmaf(f[i].w, f[i].w, sq))));
            dp = fmaf(f[i].x, p.x, fmaf(f[i].y, p.y, fmaf(f[i].z, p.z, fmaf(f[i].w, p.w, dp))));
        }
        // stage B
        uint4 wbh[2], wbl[2];
        #pragma unroll
        for (int j = 0; j < 2; j++) {
            int idx = t + j * 256;
            int n = idx >> 3, kk = (idx & 7) * 8;
            wbh[j] = *(const uint4*)(g_wd_hi + (size_t)n * 1024 + c * 64 + kk);
            wbl[j] = *(const uint4*)(g_wd_lo + (size_t)n * 1024 + c * 64 + kk);
        }
        __syncthreads();   // previous chunk's MMA reads done
        #pragma unroll
        for (int i = 0; i < 8; i += 2) {
            uint32_t h0 = pack_hi2(f[i].x, f[i].y);
            uint32_t h1 = pack_hi2(f[i].z, f[i].w);
            uint32_t h2 = pack_hi2(f[i + 1].x, f[i + 1].y);
            uint32_t h3 = pack_hi2(f[i + 1].z, f[i + 1].w);
            float2 d0 = unhi2(h0), d1 = unhi2(h1), d2 = unhi2(h2), d3 = unhi2(h3);
            uint32_t l0 = pack_hi2(f[i].x - d0.x, f[i].y - d0.y);
            uint32_t l1 = pack_hi2(f[i].z - d1.x, f[i].w - d1.y);
            uint32_t l2 = pack_hi2(f[i + 1].x - d2.x, f[i + 1].y - d2.y);
            uint32_t l3 = pack_hi2(f[i + 1].z - d3.x, f[i + 1].w - d3.y);
            int w0 = rl * AP + half * 16 + i * 2;
            *(uint4*)(Ah + w0) = make_uint4(h0, h1, h2, h3);
            *(uint4*)(Al + w0) = make_uint4(l0, l1, l2, l3);
        }
        #pragma unroll
        for (int j = 0; j < 2; j++) {
            int idx = t + j * 256;
            int n = idx >> 3, kk = (idx & 7) * 8;
            int w0 = n * AP + kk / 2;
            *(uint4*)(Bh + w0) = wbh[j];
            *(uint4*)(Bl + w0) = wbl[j];
        }
        __syncthreads();
        // MMA over this chunk
        #pragma unroll
        for (int ks = 0; ks < 4; ks++) {
            const int cb = ks * 8 + (lane & 3);
            const int ra = warpM * 32 + (lane >> 2);
            uint32_t ah[2][4], al[2][4], bh[4][2], bl[4][2];
            #pragma unroll
            for (int mt = 0; mt < 2; mt++) {
                int base = (ra + mt * 16) * AP + cb;
                ah[mt][0] = Ah[base];            ah[mt][1] = Ah[base + 8 * AP];
                ah[mt][2] = Ah[base + 4];        ah[mt][3] = Ah[base + 8 * AP + 4];
                al[mt][0] = Al[base];            al[mt][1] = Al[base + 8 * AP];
                al[mt][2] = Al[base + 4];        al[mt][3] = Al[base + 8 * AP + 4];
            }
            #pragma unroll
            for (int nt = 0; nt < 4; nt++) {
                int nb = warpN * 32 + nt * 8 + (lane >> 2);
                int base = nb * AP + cb;
                bh[nt][0] = Bh[base]; bh[nt][1] = Bh[base + 4];
                bl[nt][0] = Bl[base]; bl[nt][1] = Bl[base + 4];
            }
            #pragma unroll
            for (int mt = 0; mt < 2; mt++)
                #pragma unroll
                for (int nt = 0; nt < 4; nt++) {
                    float* d = acc[mt * 4 + nt];
                    mma_bf16(d, ah[mt][0], ah[mt][1], ah[mt][2], ah[mt][3], bh[nt][0], bh[nt][1]);
                    mma_bf16(d, ah[mt][0], ah[mt][1], ah[mt][2], ah[mt][3], bl[nt][0], bl[nt][1]);
                    mma_bf16(d, al[mt][0], al[mt][1], al[mt][2], al[mt][3], bh[nt][0], bh[nt][1]);
                }
        }
        __syncthreads();
    }
    // per-row enhancement scalar (threads 2rl,2rl+1 are adjacent lanes)
    sq += __shfl_xor_sync(0xFFFFFFFFu, sq, 1);
    dp += __shfl_xor_sync(0xFFFFFFFFu, dp, 1);
    if (half == 0) {
        float g = fminf(fmaxf(dp / fmaxf(sqrtf(sq), 1e-12f), 0.0f), 6.0f);
        sA[rl] = 1.0f + g;
    }
    __syncthreads();
    // epilogue: h = relu(a*dot + b_down) -> bf16 hi/lo
    #pragma unroll
    for (int nt = 0; nt < 4; nt++) {
        const int c0 = warpN * 32 + nt * 8 + (lane & 3) * 2;
        const float bd0 = __ldg(bdn + c0), bd1 = __ldg(bdn + c0 + 1);
        #pragma unroll
        for (int mt = 0; mt < 2; mt++) {
            const float* d = acc[mt * 4 + nt];
            const int rb = warpM * 32 + mt * 16 + (lane >> 2);
            #pragma unroll
            for (int rr = 0; rr < 2; rr++) {
                int row = row0 + rb + rr * 8;
                if (row < ROWS_TOT) {
                    float av = sA[rb + rr * 8];
                    float h0 = fmaxf(fmaf(av, d[rr * 2 + 0], bd0), 0.f);
                    float h1 = fmaxf(fmaf(av, d[rr * 2 + 1], bd1), 0.f);
                    uint32_t hp = pack_hi2(h0, h1);
                    float2 hd = unhi2(hp);
                    uint32_t lp = pack_hi2(h0 - hd.x, h1 - hd.y);
                    *(uint32_t*)(g_h_hi + (size_t)row * 64 + c0) = hp;
                    *(uint32_t*)(g_h_lo + (size_t)row * 64 + c0) = lp;
                }
            }
        }
    }
}

// ================= K5: up GEMM =================
// grid (313, 16): BM=128 rows, BN=64 cols, K=64 single chunk.
__global__ void __launch_bounds__(256, 2)
up_k(const float* __restrict__ bup, float* __restrict__ out) {
    uint32_t* Ah = smw;
    uint32_t* Al = smw + 4608;
    uint32_t* Bh = smw + 9216;
    uint32_t* Bl = smw + 11520;

    const int t = threadIdx.x, wid = t >> 5, lane = t & 31;
    const int warpM = wid & 3, warpN = wid >> 2;
    const int row0 = blockIdx.x * 128;
    const int nb64 = blockIdx.y * 64;

    // load A (128 rows x 64 k) hi/lo
    #pragma unroll
    for (int j = 0; j < 4; j++) {
        int idx = t + j * 256;
        int r = idx >> 3, kk = (idx & 7) * 8;
        int row = row0 + r;
        uint4 vh = make_uint4(0, 0, 0, 0), vl = make_uint4(0, 0, 0, 0);
        if (row < ROWS_TOT) {
            vh = *(const uint4*)(g_h_hi + (size_t)row * 64 + kk);
            vl = *(const uint4*)(g_h_lo + (size_t)row * 64 + kk);
        }
        int w0 = r * AP + kk / 2;
        *(uint4*)(Ah + w0) = vh;
        *(uint4*)(Al + w0) = vl;
    }
    // load B (64 n x 64 k) hi/lo
    #pragma unroll
    for (int j = 0; j < 2; j++) {
        int idx = t + j * 256;
        int n = idx >> 3, kk = (idx & 7) * 8;
        int w0 = n * AP + kk / 2;
        *(uint4*)(Bh + w0) = *(const uint4*)(g_wu_hi + (size_t)(nb64 + n) * 64 + kk);
        *(uint4*)(Bl + w0) = *(const uint4*)(g_wu_lo + (size_t)(nb64 + n) * 64 + kk);
    }
    __syncthreads();

    float acc[8][4];
    #pragma unroll
    for (int i = 0; i < 8; i++)
        #pragma unroll
        for (int j = 0; j < 4; j++) acc[i][j] = 0.f;

    #pragma unroll
    for (int ks = 0; ks < 4; ks++) {
        const int cb = ks * 8 + (lane & 3);
        const int ra = warpM * 32 + (lane >> 2);
        uint32_t ah[2][4], al[2][4], bh[4][2], bl[4][2];
        #pragma unroll
        for (int mt = 0; mt < 2; mt++) {
            int base = (ra + mt * 16) * AP + cb;
            ah[mt][0] = Ah[base];            ah[mt][1] = Ah[base + 8 * AP];
            ah[mt][2] = Ah[base + 4];        ah[mt][3] = Ah[base + 8 * AP + 4];
            al[mt][0] = Al[base];            al[mt][1] = Al[base + 8 * AP];
            al[mt][2] = Al[base + 4];        al[mt][3] = Al[base + 8 * AP + 4];
        }
        #pragma unroll
        for (int nt = 0; nt < 4; nt++) {
            int nb = warpN * 32 + nt * 8 + (lane >> 2);
            int base = nb * AP + cb;
            bh[nt][0] = Bh[base]; bh[nt][1] = Bh[base + 4];
            bl[nt][0] = Bl[base]; bl[nt][1] = Bl[base + 4];
        }
        #pragma unroll
        for (int mt = 0; mt < 2; mt++)
            #pragma unroll
            for (int nt = 0; nt < 4; nt++) {
                float* d = acc[mt * 4 + nt];
                mma_bf16(d, ah[mt][0], ah[mt][1], ah[mt][2], ah[mt][3], bh[nt][0], bh[nt][1]);
                mma_bf16(d, ah[mt][0], ah[mt][1], ah[mt][2], ah[mt][3], bl[nt][0], bl[nt][1]);
                mma_bf16(d, al[mt][0], al[mt][1], al[mt][2], al[mt][3], bh[nt][0], bh[nt][1]);
            }
    }

    // epilogue: out = acc + b_up
    #pragma unroll
    for (int nt = 0; nt < 4; nt++) {
        const int c0 = warpN * 32 + nt * 8 + (lane & 3) * 2;
        const float u0 = __ldg(bup + nb64 + c0), u1 = __ldg(bup + nb64 + c0 + 1);
        #pragma unroll
        for (int mt = 0; mt < 2; mt++) {
            const float* d = acc[mt * 4 + nt];
            const int rb = warpM * 32 + mt * 16 + (lane >> 2);
            #pragma unroll
            for (int rr = 0; rr < 2; rr++) {
                int row = row0 + rb + rr * 8;
                if (row < ROWS_TOT) {
                    float2 v = make_float2(d[rr * 2 + 0] + u0, d[rr * 2 + 1] + u1);
                    *(float2*)(out + (size_t)row * 1024 + nb64 + c0) = v;
                }
            }
        }
    }
}

// ---------------- launch ----------------
extern "C" void kernel_launch(void* const* d_in, const int* in_sizes, int n_in,
                              void* d_out, int out_size) {
    (void)in_sizes; (void)n_in; (void)out_size;
    const float* x   = (const float*)d_in[0];
    const float* s_f = (const float*)d_in[1];
    const float* s_y = (const float*)d_in[2];
    const float* P   = (const float*)d_in[3];
    const float* Wd  = (const float*)d_in[4];
    const float* bd  = (const float*)d_in[5];
    const float* Wu  = (const float*)d_in[6];
    const float* bu  = (const float*)d_in[7];
    float* out = (float*)d_out;

    static bool attr_set = false;
    if (!attr_set) {
        cudaFuncSetAttribute(down_k, cudaFuncAttributeMaxDynamicSharedMemorySize, 55808);
        cudaFuncSetAttribute(up_k,   cudaFuncAttributeMaxDynamicSharedMemorySize, 55296);
        attr_set = true;
    }

    zero_k<<<32, 256>>>();
    proto_sum_k<<<dim3(20, 8), 256>>>(s_f, s_y);
    prep_w_k<<<512, 256>>>(Wd, Wu);
    select_k<<<1, 256>>>(P);
    down_k<<<313, 256, 55808>>>(x, s_f, bd);
    up_k<<<dim3(313, 16), 256, 55296>>>(bu, out);
}

// round 6
// speedup vs baseline: 1.4644x; 1.1477x over previous
#include <cuda_runtime.h>
#include <cuda_bf16.h>
#include <cstdint>

#define ROWS_TOT 40000
#define ROWS_SF  20000
#define AP 36            // smem row stride in 32-bit words (= 72 bf16, conflict-free)

// ---------------- scratch (static device globals; no runtime allocation) ----------------
__device__ float g_psum[8 * 1024];
__device__ float g_cnt[8];
__device__ float g_pvec[8 * 1024];
__device__ float g_norm2[16];
__device__ float g_sims[8 * 16];
__device__ __align__(16) __nv_bfloat16 g_wd_hi[64 * 1024];
__device__ __align__(16) __nv_bfloat16 g_wd_lo[64 * 1024];
__device__ __align__(16) __nv_bfloat16 g_wu_hi[1024 * 64];
__device__ __align__(16) __nv_bfloat16 g_wu_lo[1024 * 64];

// ---------------- helpers ----------------
__device__ __forceinline__ void mma_bf16(float* d, uint32_t a0, uint32_t a1, uint32_t a2,
                                         uint32_t a3, uint32_t b0, uint32_t b1) {
    asm volatile(
        "mma.sync.aligned.m16n8k16.row.col.f32.bf16.bf16.f32 "
        "{%0,%1,%2,%3}, {%4,%5,%6,%7}, {%8,%9}, {%0,%1,%2,%3};"
        : "+f"(d[0]), "+f"(d[1]), "+f"(d[2]), "+f"(d[3])
        : "r"(a0), "r"(a1), "r"(a2), "r"(a3), "r"(b0), "r"(b1));
}
__device__ __forceinline__ uint32_t pack_hi2(float x, float y) {
    __nv_bfloat162 h = __float22bfloat162_rn(make_float2(x, y));
    return *reinterpret_cast<uint32_t*>(&h);
}
__device__ __forceinline__ float2 unhi2(uint32_t u) {
    __nv_bfloat162 h = *reinterpret_cast<__nv_bfloat162*>(&u);
    return make_float2(__low2float(h), __high2float(h));
}

// ---------------- K0: zero accumulators ----------------
__global__ void zero_k() {
    int i = blockIdx.x * 256 + threadIdx.x;
    if (i < 8192) g_psum[i] = 0.0f;
    if (i < 8)    g_cnt[i]  = 0.0f;
}

// ---------------- K1: masked prototype sum ----------------
__global__ void proto_sum_k(const float* __restrict__ s_f, const float* __restrict__ s_y) {
    const int b  = blockIdx.y;
    const int n0 = blockIdx.x * 125;
    const int t  = threadIdx.x;
    const float* sy = s_y + (size_t)b * 160000;
    float4 acc = make_float4(0.f, 0.f, 0.f, 0.f);
    int cnt = 0;
    for (int n = n0; n < n0 + 125; n++) {
        float m = sy[(n / 50) * 3200 + (n % 50) * 8];   // nearest-neighbor stride-8
        if (m == 1.0f) {
            float4 v = *(const float4*)(s_f + (size_t)(b * 2500 + n) * 1024 + t * 4);
            acc.x += v.x; acc.y += v.y; acc.z += v.z; acc.w += v.w;
            cnt++;
        }
    }
    float* ps = g_psum + b * 1024 + t * 4;
    atomicAdd(ps + 0, acc.x); atomicAdd(ps + 1, acc.y);
    atomicAdd(ps + 2, acc.z); atomicAdd(ps + 3, acc.w);
    if (t == 0) atomicAdd(&g_cnt[b], (float)cnt);
}

// ---------------- K2a: sims + norms, fully parallel ----------------
// grid (16, 9): x = class c; y<8 = batch dot, y==8 = column norm. 256 threads.
__global__ void sims_k(const float* __restrict__ P) {    // P: [1024,16]
    __shared__ float red[8];
    const int c = blockIdx.x, b = blockIdx.y;
    const int t = threadIdx.x, lane = t & 31, w = t >> 5;
    float s = 0.f;
    if (b == 8) {
        #pragma unroll
        for (int i = 0; i < 4; i++) { float v = P[(t + i * 256) * 16 + c]; s = fmaf(v, v, s); }
    } else {
        const float* ps = g_psum + b * 1024;
        #pragma unroll
        for (int i = 0; i < 4; i++) { int d = t + i * 256; s = fmaf(ps[d], P[d * 16 + c], s); }
    }
    #pragma unroll
    for (int o = 16; o; o >>= 1) s += __shfl_xor_sync(0xFFFFFFFFu, s, o);
    if (!lane) red[w] = s;
    __syncthreads();
    if (t == 0) {
        float tot = 0.f;
        #pragma unroll
        for (int i = 0; i < 8; i++) tot += red[i];
        if (b == 8) g_norm2[c] = tot;
        else        g_sims[b * 16 + c] = tot;
    }
}

// ---------------- K2b: per-batch argmax + pvec write (grid 8) ----------------
__global__ void finish_k(const float* __restrict__ P) {
    const int b = blockIdx.x, t = threadIdx.x;
    __shared__ int   ssel;
    __shared__ float sfac;
    if (t == 0) {
        int best = 0; float bv = -1e30f;
        #pragma unroll
        for (int c = 0; c < 16; c++) {
            float v = g_sims[b * 16 + c] * rsqrtf(fmaxf(g_norm2[c], 1e-24f));
            if (v > bv) { bv = v; best = c; }
        }
        ssel = best;
        float sign = (g_cnt[b] > 0.5f) ? 1.0f : 0.0f;
        sfac = sign * 32.0f * rsqrtf(fmaxf(g_norm2[best], 1e-24f));
    }
    __syncthreads();
    const int sel = ssel; const float fac = sfac;
    #pragma unroll
    for (int i = 0; i < 4; i++) {
        int d = t + i * 256;
        g_pvec[b * 1024 + d] = P[d * 16 + sel] * fac;
    }
}

// ---------------- K3: weight prep (bf16 hi/lo) ----------------
__global__ void prep_w_k(const float* __restrict__ Wd, const float* __restrict__ Wu) {
    int i = blockIdx.x * 256 + threadIdx.x;
    if (i < 65536) {                       // Wd [64][1024]
        float v = Wd[i];
        __nv_bfloat16 h = __float2bfloat16_rn(v);
        g_wd_hi[i] = h;
        g_wd_lo[i] = __float2bfloat16_rn(v - __bfloat162float(h));
    } else if (i < 131072) {               // Wu [1024][64]
        i -= 65536;
        float v = Wu[i];
        __nv_bfloat16 h = __float2bfloat16_rn(v);
        g_wu_hi[i] = h;
        g_wu_lo[i] = __float2bfloat16_rn(v - __bfloat162float(h));
    }
}

// ================= K4: fused enhance + down GEMM + up GEMM =================
// grid 313, BM=128. 256 thr = 8 warps (4 m x 2 n).
// smem words: Ah[0,4608) Al[4608,9216) Bh[9216,11520) Bl[11520,13824) a[13824,13952)
// After the down phase, Ah/Al are reused to hold h (128 x 64 bf16) hi/lo.
extern __shared__ uint32_t smw[];

__global__ void __launch_bounds__(256, 2)
fused_k(const float* __restrict__ x, const float* __restrict__ s_f,
        const float* __restrict__ bdn, const float* __restrict__ bup,
        float* __restrict__ out) {
    uint32_t* Ah = smw;
    uint32_t* Al = smw + 4608;
    uint32_t* Bh = smw + 9216;
    uint32_t* Bl = smw + 11520;
    float*    sA = (float*)(smw + 13824);

    const int t = threadIdx.x, wid = t >> 5, lane = t & 31;
    const int warpM = wid & 3, warpN = wid >> 2;
    const int row0 = blockIdx.x * 128;
    const int rl = t >> 1, half = t & 1;
    const int grow = row0 + rl;
    const bool rok = grow < ROWS_TOT;
    const float* src = rok ? ((grow < ROWS_SF) ? s_f + (size_t)grow * 1024
                                               : x + (size_t)(grow - ROWS_SF) * 1024)
                           : x;
    const int bb = rok ? ((grow < ROWS_SF) ? grow / 2500 : (grow - ROWS_SF) / 2500) : 0;
    const float* pvp = g_pvec + bb * 1024 + half * 32;

    float acc[8][4];
    #pragma unroll
    for (int i = 0; i < 8; i++)
        #pragma unroll
        for (int j = 0; j < 4; j++) acc[i][j] = 0.f;

    float sq = 0.f, dp = 0.f;

    // ============ down phase: K=1024 in 16 chunks of 64 ============
    for (int c = 0; c < 16; c++) {
        const int kb = c * 64 + half * 32;
        float4 f[8];
        #pragma unroll
        for (int i = 0; i < 8; i++) {
            f[i] = rok ? *(const float4*)(src + kb + i * 4) : make_float4(0.f, 0.f, 0.f, 0.f);
            float4 p = *(const float4*)(pvp + c * 64 + i * 4);
            sq = fmaf(f[i].x, f[i].x, fmaf(f[i].y, f[i].y, fmaf(f[i].z, f[i].z, fmaf(f[i].w, f[i].w, sq))));
            dp = fmaf(f[i].x, p.x, fmaf(f[i].y, p.y, fmaf(f[i].z, p.z, fmaf(f[i].w, p.w, dp))));
        }
        uint4 wbh[2], wbl[2];
        #pragma unroll
        for (int j = 0; j < 2; j++) {
            int idx = t + j * 256;
            int n = idx >> 3, kk = (idx & 7) * 8;
            wbh[j] = *(const uint4*)(g_wd_hi + (size_t)n * 1024 + c * 64 + kk);
            wbl[j] = *(const uint4*)(g_wd_lo + (size_t)n * 1024 + c * 64 + kk);
        }
        __syncthreads();   // previous chunk's MMA reads done
        #pragma unroll
        for (int i = 0; i < 8; i += 2) {
            uint32_t h0 = pack_hi2(f[i].x, f[i].y);
            uint32_t h1 = pack_hi2(f[i].z, f[i].w);
            uint32_t h2 = pack_hi2(f[i + 1].x, f[i + 1].y);
            uint32_t h3 = pack_hi2(f[i + 1].z, f[i + 1].w);
            float2 d0 = unhi2(h0), d1 = unhi2(h1), d2 = unhi2(h2), d3 = unhi2(h3);
            uint32_t l0 = pack_hi2(f[i].x - d0.x, f[i].y - d0.y);
            uint32_t l1 = pack_hi2(f[i].z - d1.x, f[i].w - d1.y);
            uint32_t l2 = pack_hi2(f[i + 1].x - d2.x, f[i + 1].y - d2.y);
            uint32_t l3 = pack_hi2(f[i + 1].z - d3.x, f[i + 1].w - d3.y);
            int w0 = rl * AP + half * 16 + i * 2;
            *(uint4*)(Ah + w0) = make_uint4(h0, h1, h2, h3);
            *(uint4*)(Al + w0) = make_uint4(l0, l1, l2, l3);
        }
        #pragma unroll
        for (int j = 0; j < 2; j++) {
            int idx = t + j * 256;
            int n = idx >> 3, kk = (idx & 7) * 8;
            int w0 = n * AP + kk / 2;
            *(uint4*)(Bh + w0) = wbh[j];
            *(uint4*)(Bl + w0) = wbl[j];
        }
        __syncthreads();
        #pragma unroll
        for (int ks = 0; ks < 4; ks++) {
            const int cb = ks * 8 + (lane & 3);
            const int ra = warpM * 32 + (lane >> 2);
            uint32_t ah[2][4], al[2][4], bh[4][2], bl[4][2];
            #pragma unroll
            for (int mt = 0; mt < 2; mt++) {
                int base = (ra + mt * 16) * AP + cb;
                ah[mt][0] = Ah[base];            ah[mt][1] = Ah[base + 8 * AP];
                ah[mt][2] = Ah[base + 4];        ah[mt][3] = Ah[base + 8 * AP + 4];
                al[mt][0] = Al[base];            al[mt][1] = Al[base + 8 * AP];
                al[mt][2] = Al[base + 4];        al[mt][3] = Al[base + 8 * AP + 4];
            }
            #pragma unroll
            for (int nt = 0; nt < 4; nt++) {
                int nb = warpN * 32 + nt * 8 + (lane >> 2);
                int base = nb * AP + cb;
                bh[nt][0] = Bh[base]; bh[nt][1] = Bh[base + 4];
                bl[nt][0] = Bl[base]; bl[nt][1] = Bl[base + 4];
            }
            #pragma unroll
            for (int mt = 0; mt < 2; mt++)
                #pragma unroll
                for (int nt = 0; nt < 4; nt++) {
                    float* d = acc[mt * 4 + nt];
                    mma_bf16(d, ah[mt][0], ah[mt][1], ah[mt][2], ah[mt][3], bh[nt][0], bh[nt][1]);
                    mma_bf16(d, ah[mt][0], ah[mt][1], ah[mt][2], ah[mt][3], bl[nt][0], bl[nt][1]);
                    mma_bf16(d, al[mt][0], al[mt][1], al[mt][2], al[mt][3], bh[nt][0], bh[nt][1]);
                }
        }
        __syncthreads();
    }
    // per-row enhancement scalar (threads 2rl,2rl+1 are adjacent lanes)
    sq += __shfl_xor_sync(0xFFFFFFFFu, sq, 1);
    dp += __shfl_xor_sync(0xFFFFFFFFu, dp, 1);
    if (half == 0) {
        float g = fminf(fmaxf(dp / fmaxf(sqrtf(sq), 1e-12f), 0.0f), 6.0f);
        sA[rl] = 1.0f + g;
    }
    __syncthreads();

    // ---- down epilogue: h = relu(a*dot + b_down) -> bf16 hi/lo into Ah/Al ----
    #pragma unroll
    for (int nt = 0; nt < 4; nt++) {
        const int c0 = warpN * 32 + nt * 8 + (lane & 3) * 2;
        const float bd0 = __ldg(bdn + c0), bd1 = __ldg(bdn + c0 + 1);
        #pragma unroll
        for (int mt = 0; mt < 2; mt++) {
            const float* d = acc[mt * 4 + nt];
            const int rb = warpM * 32 + mt * 16 + (lane >> 2);
            #pragma unroll
            for (int rr = 0; rr < 2; rr++) {
                const int rloc = rb + rr * 8;
                float av = sA[rloc];
                float h0 = fmaxf(fmaf(av, d[rr * 2 + 0], bd0), 0.f);
                float h1 = fmaxf(fmaf(av, d[rr * 2 + 1], bd1), 0.f);
                uint32_t hp = pack_hi2(h0, h1);
                float2 hd = unhi2(hp);
                uint32_t lp = pack_hi2(h0 - hd.x, h1 - hd.y);
                Ah[rloc * AP + c0 / 2] = hp;
                Al[rloc * AP + c0 / 2] = lp;
            }
        }
    }

    // ============ up phase: 16 N-chunks of 64, A = h (in smem) ============
    for (int nc = 0; nc < 16; nc++) {
        const int nb64 = nc * 64;
        uint4 wbh[2], wbl[2];
        #pragma unroll
        for (int j = 0; j < 2; j++) {
            int idx = t + j * 256;
            int n = idx >> 3, kk = (idx & 7) * 8;
            wbh[j] = *(const uint4*)(g_wu_hi + (size_t)(nb64 + n) * 64 + kk);
            wbl[j] = *(const uint4*)(g_wu_lo + (size_t)(nb64 + n) * 64 + kk);
        }
        __syncthreads();   // prev chunk MMA reads of B done (and h stores visible on nc==0)
        #pragma unroll
        for (int j = 0; j < 2; j++) {
            int idx = t + j * 256;
            int n = idx >> 3, kk = (idx & 7) * 8;
            int w0 = n * AP + kk / 2;
            *(uint4*)(Bh + w0) = wbh[j];
            *(uint4*)(Bl + w0) = wbl[j];
        }
        __syncthreads();

        #pragma unroll
        for (int i = 0; i < 8; i++)
            #pragma unroll
            for (int j = 0; j < 4; j++) acc[i][j] = 0.f;

        #pragma unroll
        for (int ks = 0; ks < 4; ks++) {
            const int cb = ks * 8 + (lane & 3);
            const int ra = warpM * 32 + (lane >> 2);
            uint32_t ah[2][4], al[2][4], bh[4][2], bl[4][2];
            #pragma unroll
            for (int mt = 0; mt < 2; mt++) {
                int base = (ra + mt * 16) * AP + cb;
                ah[mt][0] = Ah[base];            ah[mt][1] = Ah[base + 8 * AP];
                ah[mt][2] = Ah[base + 4];        ah[mt][3] = Ah[base + 8 * AP + 4];
                al[mt][0] = Al[base];            al[mt][1] = Al[base + 8 * AP];
                al[mt][2] = Al[base + 4];        al[mt][3] = Al[base + 8 * AP + 4];
            }
            #pragma unroll
            for (int nt = 0; nt < 4; nt++) {
                int nb = warpN * 32 + nt * 8 + (lane >> 2);
                int base = nb * AP + cb;
                bh[nt][0] = Bh[base]; bh[nt][1] = Bh[base + 4];
                bl[nt][0] = Bl[base]; bl[nt][1] = Bl[base + 4];
            }
            #pragma unroll
            for (int mt = 0; mt < 2; mt++)
                #pragma unroll
                for (int nt = 0; nt < 4; nt++) {
                    float* d = acc[mt * 4 + nt];
                    mma_bf16(d, ah[mt][0], ah[mt][1], ah[mt][2], ah[mt][3], bh[nt][0], bh[nt][1]);
                    mma_bf16(d, ah[mt][0], ah[mt][1], ah[mt][2], ah[mt][3], bl[nt][0], bl[nt][1]);
                    mma_bf16(d, al[mt][0], al[mt][1], al[mt][2], al[mt][3], bh[nt][0], bh[nt][1]);
                }
        }

        // epilogue: out = acc + b_up
        #pragma unroll
        for (int nt = 0; nt < 4; nt++) {
            const int c0 = warpN * 32 + nt * 8 + (lane & 3) * 2;
            const float u0 = __ldg(bup + nb64 + c0), u1 = __ldg(bup + nb64 + c0 + 1);
            #pragma unroll
            for (int mt = 0; mt < 2; mt++) {
                const float* d = acc[mt * 4 + nt];
                const int rb = warpM * 32 + mt * 16 + (lane >> 2);
                #pragma unroll
                for (int rr = 0; rr < 2; rr++) {
                    int row = row0 + rb + rr * 8;
                    if (row < ROWS_TOT) {
                        float2 v = make_float2(d[rr * 2 + 0] + u0, d[rr * 2 + 1] + u1);
                        *(float2*)(out + (size_t)row * 1024 + nb64 + c0) = v;
                    }
                }
            }
        }
    }
}

// ---------------- launch ----------------
extern "C" void kernel_launch(void* const* d_in, const int* in_sizes, int n_in,
                              void* d_out, int out_size) {
    (void)in_sizes; (void)n_in; (void)out_size;
    const float* x   = (const float*)d_in[0];
    const float* s_f = (const float*)d_in[1];
    const float* s_y = (const float*)d_in[2];
    const float* P   = (const float*)d_in[3];
    const float* Wd  = (const float*)d_in[4];
    const float* bd  = (const float*)d_in[5];
    const float* Wu  = (const float*)d_in[6];
    const float* bu  = (const float*)d_in[7];
    float* out = (float*)d_out;

    static bool attr_set = false;
    if (!attr_set) {
        cudaFuncSetAttribute(fused_k, cudaFuncAttributeMaxDynamicSharedMemorySize, 55808);
        attr_set = true;
    }

    zero_k<<<32, 256>>>();
    proto_sum_k<<<dim3(20, 8), 256>>>(s_f, s_y);
    prep_w_k<<<512, 256>>>(Wd, Wu);
    sims_k<<<dim3(16, 9), 256>>>(P);
    finish_k<<<8, 256>>>(P);
    fused_k<<<313, 256, 55808>>>(x, s_f, bd, bu, out);
}

// round 9
// speedup vs baseline: 1.7520x; 1.1964x over previous
#include <cuda_runtime.h>
#include <cuda_fp16.h>
#include <cstdint>

#define ROWS_TOT 40000
#define ROWS_SF  20000

// ---------------- scratch (static device globals; no runtime allocation) ----------------
__device__ float g_psum[8 * 1024];
__device__ float g_cnt[8];
__device__ float g_pvec[8 * 1024];
__device__ __align__(16) __half g_wd_hi[16 * 64 * 64];   // [chunk][n][k] fp16
__device__ __align__(16) __half g_wd_lo[16 * 64 * 64];
__device__ __align__(16) __half g_wu_hi[1024 * 64];      // [n][k] fp16 (chunk = n/64)
__device__ __align__(16) __half g_wu_lo[1024 * 64];

// ---------------- helpers ----------------
__device__ __forceinline__ void mma_f16(float* d, uint32_t a0, uint32_t a1, uint32_t a2,
                                        uint32_t a3, uint32_t b0, uint32_t b1) {
    asm volatile(
        "mma.sync.aligned.m16n8k16.row.col.f32.f16.f16.f32 "
        "{%0,%1,%2,%3}, {%4,%5,%6,%7}, {%8,%9}, {%0,%1,%2,%3};"
        : "+f"(d[0]), "+f"(d[1]), "+f"(d[2]), "+f"(d[3])
        : "r"(a0), "r"(a1), "r"(a2), "r"(a3), "r"(b0), "r"(b1));
}
__device__ __forceinline__ void ldsm_x4(uint32_t addr, uint32_t* r) {
    asm volatile("ldmatrix.sync.aligned.m8n8.x4.shared.b16 {%0,%1,%2,%3}, [%4];"
                 : "=r"(r[0]), "=r"(r[1]), "=r"(r[2]), "=r"(r[3]) : "r"(addr));
}
__device__ __forceinline__ uint32_t smem_u32(const void* p) {
    uint32_t a;
    asm("{ .reg .u64 t; cvta.to.shared.u64 t, %1; cvt.u32.u64 %0, t; }" : "=r"(a) : "l"(p));
    return a;
}
__device__ __forceinline__ uint32_t pkh2(float x, float y) {
    __half2 h = __float22half2_rn(make_float2(x, y));
    return *reinterpret_cast<uint32_t*>(&h);
}

// ---------------- K1: zero + weight prep (fp16 hi/lo) ----------------
__global__ void prep0_k(const float* __restrict__ Wd, const float* __restrict__ Wu) {
    int i = blockIdx.x * 256 + threadIdx.x;
    if (i < 8192) g_psum[i] = 0.0f;
    if (i < 8)    g_cnt[i]  = 0.0f;
    if (i < 65536) {                       // Wd [64][1024] -> chunked [16][64][64]
        int n = i >> 10, kk = i & 1023;
        int c = kk >> 6, k = kk & 63;
        float v = Wd[i];
        __half h = __float2half_rn(v);
        __half l = __float2half_rn(v - __half2float(h));
        int o = c * 4096 + n * 64 + k;
        g_wd_hi[o] = h; g_wd_lo[o] = l;
    } else if (i < 131072) {               // Wu [1024][64]
        int j = i - 65536;
        float v = Wu[j];
        __half h = __float2half_rn(v);
        __half l = __float2half_rn(v - __half2float(h));
        g_wu_hi[j] = h; g_wu_lo[j] = l;
    }
}

// ---------------- K2: masked prototype sum ----------------
__global__ void proto_sum_k(const float* __restrict__ s_f, const float* __restrict__ s_y) {
    const int b  = blockIdx.y;
    const int n0 = blockIdx.x * 125;
    const int t  = threadIdx.x;
    const float* sy = s_y + (size_t)b * 160000;
    float4 acc = make_float4(0.f, 0.f, 0.f, 0.f);
    int cnt = 0;
    for (int n = n0; n < n0 + 125; n++) {
        float m = sy[(n / 50) * 3200 + (n % 50) * 8];   // nearest-neighbor stride-8
        if (m == 1.0f) {
            float4 v = *(const float4*)(s_f + (size_t)(b * 2500 + n) * 1024 + t * 4);
            acc.x += v.x; acc.y += v.y; acc.z += v.z; acc.w += v.w;
            cnt++;
        }
    }
    float* ps = g_psum + b * 1024 + t * 4;
    atomicAdd(ps + 0, acc.x); atomicAdd(ps + 1, acc.y);
    atomicAdd(ps + 2, acc.z); atomicAdd(ps + 3, acc.w);
    if (t == 0) atomicAdd(&g_cnt[b], (float)cnt);
}

// ---------------- K3: prototype selection (grid 8 = one CTA per batch) ----------------
__global__ void select2_k(const float* __restrict__ P) {   // P: [1024][16]
    __shared__ float s_sim[16], s_n2[16];
    __shared__ int   ssel;
    __shared__ float sfac;
    const int b = blockIdx.x, t = threadIdx.x, lane = t & 31, w = t >> 5;
    const float* ps = g_psum + b * 1024;
    for (int c = w; c < 16; c += 8) {
        float sd = 0.f, sn = 0.f;
        for (int d = lane; d < 1024; d += 32) {
            float pv = P[d * 16 + c];
            sd = fmaf(ps[d], pv, sd);
            sn = fmaf(pv, pv, sn);
        }
        #pragma unroll
        for (int o = 16; o; o >>= 1) {
            sd += __shfl_xor_sync(0xFFFFFFFFu, sd, o);
            sn += __shfl_xor_sync(0xFFFFFFFFu, sn, o);
        }
        if (!lane) { s_sim[c] = sd; s_n2[c] = sn; }
    }
    __syncthreads();
    if (t == 0) {
        int best = 0; float bv = -1e30f;
        #pragma unroll
        for (int c = 0; c < 16; c++) {
            float v = s_sim[c] * rsqrtf(fmaxf(s_n2[c], 1e-24f));
            if (v > bv) { bv = v; best = c; }
        }
        ssel = best;
        float sign = (g_cnt[b] > 0.5f) ? 1.0f : 0.0f;
        sfac = sign * 32.0f * rsqrtf(fmaxf(s_n2[best], 1e-24f));
    }
    __syncthreads();
    const int sel = ssel; const float fac = sfac;
    #pragma unroll
    for (int i = 0; i < 4; i++) {
        int d = t + i * 256;
        g_pvec[b * 1024 + d] = P[d * 16 + sel] * fac;
    }
}

// ================= K4: fused enhance + down GEMM + up GEMM (fp16 HMMA) =================
// grid 313, BM=128. 256 thr = 8 warps (4 warpM x 2 warpN).
// smem bytes: A[0,18432) Bh[18432,27648) Bl[27648,36864) sA[36864,37376)
// row stride 144 B (36 words) => conflict-free for stores and ldmatrix.
#define SM_BYTES 37376
extern __shared__ uint32_t smw[];

__global__ void __launch_bounds__(256, 2)
fused_k(const float* __restrict__ x, const float* __restrict__ s_f,
        const float* __restrict__ bdn, const float* __restrict__ bup,
        float* __restrict__ out) {
    uint32_t* Aw = smw;                       // word offsets
    uint32_t* BhW = smw + 4608;
    uint32_t* BlW = smw + 6912;
    float*    sA  = (float*)(smw + 9216);

    const uint32_t sbase = smem_u32(smw);
    const int t = threadIdx.x, wid = t >> 5, lane = t & 31;
    const int warpM = wid & 3, warpN = wid >> 2;
    const int row0 = blockIdx.x * 128;
    const int rl = t >> 1, half = t & 1;
    const int grow = row0 + rl;
    const bool rok = grow < ROWS_TOT;
    const float* src = rok ? ((grow < ROWS_SF) ? s_f + (size_t)grow * 1024
                                               : x + (size_t)(grow - ROWS_SF) * 1024)
                           : x;
    const int bb = rok ? ((grow < ROWS_SF) ? grow / 2500 : (grow - ROWS_SF) / 2500) : 0;
    const float* pvp = g_pvec + bb * 1024 + half * 32;

    // ldmatrix per-lane base addresses (byte)
    const int lr16 = lane & 15, lk16 = (lane >> 4) & 1;     // A: rows, k-halves
    const uint32_t aAddr0 = sbase + (uint32_t)((warpM * 32 + lr16) * 144 + lk16 * 16);
    const int br = warpN * 32 + ((lane >> 4) & 1) * 8 + (lane & 7);   // B row
    const uint32_t bOff = (uint32_t)(br * 144 + ((lane >> 3) & 1) * 16);
    const uint32_t bhAddr0 = sbase + 18432 + bOff;
    const uint32_t blAddr0 = sbase + 27648 + bOff;

    float acc[8][4];
    #pragma unroll
    for (int i = 0; i < 8; i++)
        #pragma unroll
        for (int j = 0; j < 4; j++) acc[i][j] = 0.f;

    float sq = 0.f, dp = 0.f;
    float4 f[8];
    uint4 wbh[2], wbl[2];

    // chunk-0 prefetch
    #pragma unroll
    for (int i = 0; i < 8; i++)
        f[i] = rok ? *(const float4*)(src + half * 32 + i * 4) : make_float4(0.f, 0.f, 0.f, 0.f);
    #pragma unroll
    for (int j = 0; j < 2; j++) {
        int idx = t + j * 256;
        int n = idx >> 3, q = idx & 7;
        wbh[j] = *(const uint4*)(g_wd_hi + n * 64 + q * 8);
        wbl[j] = *(const uint4*)(g_wd_lo + n * 64 + q * 8);
    }

    // ============ down phase: K=1024 in 16 chunks of 64 ============
    #pragma unroll 1
    for (int c = 0; c < 16; c++) {
        // convert + accumulate sq/dp
        uint32_t av[16];
        #pragma unroll
        for (int i = 0; i < 8; i++) {
            float4 p = *(const float4*)(pvp + c * 64 + i * 4);
            sq = fmaf(f[i].x, f[i].x, fmaf(f[i].y, f[i].y, fmaf(f[i].z, f[i].z, fmaf(f[i].w, f[i].w, sq))));
            dp = fmaf(f[i].x, p.x, fmaf(f[i].y, p.y, fmaf(f[i].z, p.z, fmaf(f[i].w, p.w, dp))));
            av[i * 2 + 0] = pkh2(f[i].x, f[i].y);
            av[i * 2 + 1] = pkh2(f[i].z, f[i].w);
        }
        __syncthreads();   // all warps done with previous chunk's tiles
        {
            int w0 = rl * 36 + half * 16;
            #pragma unroll
            for (int j = 0; j < 4; j++)
                *(uint4*)(Aw + w0 + j * 4) = make_uint4(av[j * 4], av[j * 4 + 1], av[j * 4 + 2], av[j * 4 + 3]);
            #pragma unroll
            for (int j = 0; j < 2; j++) {
                int idx = t + j * 256;
                int n = idx >> 3, q = idx & 7;
                *(uint4*)(BhW + n * 36 + q * 4) = wbh[j];
                *(uint4*)(BlW + n * 36 + q * 4) = wbl[j];
            }
        }
        __syncthreads();
        // prefetch next chunk (overlaps MMA below)
        if (c < 15) {
            const int kb = (c + 1) * 64 + half * 32;
            #pragma unroll
            for (int i = 0; i < 8; i++)
                f[i] = rok ? *(const float4*)(src + kb + i * 4) : make_float4(0.f, 0.f, 0.f, 0.f);
            #pragma unroll
            for (int j = 0; j < 2; j++) {
                int idx = t + j * 256;
                int n = idx >> 3, q = idx & 7;
                wbh[j] = *(const uint4*)(g_wd_hi + (c + 1) * 4096 + n * 64 + q * 8);
                wbl[j] = *(const uint4*)(g_wd_lo + (c + 1) * 4096 + n * 64 + q * 8);
            }
        }
        // MMA over this chunk
        #pragma unroll
        for (int ks = 0; ks < 4; ks++) {
            uint32_t af[2][4], bh[2][4], bl[2][4];
            ldsm_x4(aAddr0 + ks * 32, af[0]);
            ldsm_x4(aAddr0 + 16 * 144 + ks * 32, af[1]);
            ldsm_x4(bhAddr0 + ks * 32, bh[0]);
            ldsm_x4(bhAddr0 + 16 * 144 + ks * 32, bh[1]);
            ldsm_x4(blAddr0 + ks * 32, bl[0]);
            ldsm_x4(blAddr0 + 16 * 144 + ks * 32, bl[1]);
            #pragma unroll
            for (int mt = 0; mt < 2; mt++)
                #pragma unroll
                for (int nt = 0; nt < 4; nt++) {
                    float* d = acc[mt * 4 + nt];
                    const int n2 = nt >> 1, s = (nt & 1) * 2;
                    mma_f16(d, af[mt][0], af[mt][1], af[mt][2], af[mt][3], bh[n2][s], bh[n2][s + 1]);
                    mma_f16(d, af[mt][0], af[mt][1], af[mt][2], af[mt][3], bl[n2][s], bl[n2][s + 1]);
                }
        }
    }
    // per-row enhancement scalar
    sq += __shfl_xor_sync(0xFFFFFFFFu, sq, 1);
    dp += __shfl_xor_sync(0xFFFFFFFFu, dp, 1);
    __syncthreads();   // all warps done reading tiles of last chunk
    if (half == 0) {
        float g = fminf(fmaxf(dp / fmaxf(sqrtf(sq), 1e-12f), 0.0f), 6.0f);
        sA[rl] = 1.0f + g;
    }
    __syncthreads();

    // ---- down epilogue: h = relu(a*dot + b_down) -> fp16 into A plane ----
    #pragma unroll
    for (int nt = 0; nt < 4; nt++) {
        const int c0 = warpN * 32 + nt * 8 + (lane & 3) * 2;
        const float bd0 = __ldg(bdn + c0), bd1 = __ldg(bdn + c0 + 1);
        #pragma unroll
        for (int mt = 0; mt < 2; mt++) {
            const float* d = acc[mt * 4 + nt];
            const int rb = warpM * 32 + mt * 16 + (lane >> 2);
            #pragma unroll
            for (int rr = 0; rr < 2; rr++) {
                const int rloc = rb + rr * 8;
                float av2 = sA[rloc];
                float h0 = fmaxf(fmaf(av2, d[rr * 2 + 0], bd0), 0.f);
                float h1 = fmaxf(fmaf(av2, d[rr * 2 + 1], bd1), 0.f);
                Aw[rloc * 36 + c0 / 2] = pkh2(h0, h1);
            }
        }
    }
    // prefetch up-phase chunk 0 B
    #pragma unroll
    for (int j = 0; j < 2; j++) {
        int idx = t + j * 256;
        int n = idx >> 3, q = idx & 7;
        wbh[j] = *(const uint4*)(g_wu_hi + n * 64 + q * 8);
        wbl[j] = *(const uint4*)(g_wu_lo + n * 64 + q * 8);
    }
    __syncthreads();   // h visible

    // ============ up phase: 16 N-chunks of 64, A = h (in smem) ============
    #pragma unroll 1
    for (int nc = 0; nc < 16; nc++) {
        #pragma unroll
        for (int j = 0; j < 2; j++) {
            int idx = t + j * 256;
            int n = idx >> 3, q = idx & 7;
            *(uint4*)(BhW + n * 36 + q * 4) = wbh[j];
            *(uint4*)(BlW + n * 36 + q * 4) = wbl[j];
        }
        __syncthreads();
        if (nc < 15) {
            #pragma unroll
            for (int j = 0; j < 2; j++) {
                int idx = t + j * 256;
                int n = idx >> 3, q = idx & 7;
                wbh[j] = *(const uint4*)(g_wu_hi + (nc + 1) * 4096 + n * 64 + q * 8);
                wbl[j] = *(const uint4*)(g_wu_lo + (nc + 1) * 4096 + n * 64 + q * 8);
            }
        }
        #pragma unroll
        for (int i = 0; i < 8; i++)
            #pragma unroll
            for (int j = 0; j < 4; j++) acc[i][j] = 0.f;

        #pragma unroll
        for (int ks = 0; ks < 4; ks++) {
            uint32_t af[2][4], bh[2][4], bl[2][4];
            ldsm_x4(aAddr0 + ks * 32, af[0]);
            ldsm_x4(aAddr0 + 16 * 144 + ks * 32, af[1]);
            ldsm_x4(bhAddr0 + ks * 32, bh[0]);
            ldsm_x4(bhAddr0 + 16 * 144 + ks * 32, bh[1]);
            ldsm_x4(blAddr0 + ks * 32, bl[0]);
            ldsm_x4(blAddr0 + 16 * 144 + ks * 32, bl[1]);
            #pragma unroll
            for (int mt = 0; mt < 2; mt++)
                #pragma unroll
                for (int nt = 0; nt < 4; nt++) {
                    float* d = acc[mt * 4 + nt];
                    const int n2 = nt >> 1, s = (nt & 1) * 2;
                    mma_f16(d, af[mt][0], af[mt][1], af[mt][2], af[mt][3], bh[n2][s], bh[n2][s + 1]);
                    mma_f16(d, af[mt][0], af[mt][1], af[mt][2], af[mt][3], bl[n2][s], bl[n2][s + 1]);
                }
        }

        // epilogue: out = acc + b_up
        const int nb64 = nc * 64;
        #pragma unroll
        for (int nt = 0; nt < 4; nt++) {
            const int c0 = warpN * 32 + nt * 8 + (lane & 3) * 2;
            const float u0 = __ldg(bup + nb64 + c0), u1 = __ldg(bup + nb64 + c0 + 1);
            #pragma unroll
            for (int mt = 0; mt < 2; mt++) {
                const float* d = acc[mt * 4 + nt];
                const int rb = warpM * 32 + mt * 16 + (lane >> 2);
                #pragma unroll
                for (int rr = 0; rr < 2; rr++) {
                    int row = row0 + rb + rr * 8;
                    if (row < ROWS_TOT) {
                        float2 v = make_float2(d[rr * 2 + 0] + u0, d[rr * 2 + 1] + u1);
                        *(float2*)(out + (size_t)row * 1024 + nb64 + c0) = v;
                    }
                }
            }
        }
        __syncthreads();   // all warps done reading B before next store
    }
}

// ---------------- launch ----------------
extern "C" void kernel_launch(void* const* d_in, const int* in_sizes, int n_in,
                              void* d_out, int out_size) {
    (void)in_sizes; (void)n_in; (void)out_size;
    const float* x   = (const float*)d_in[0];
    const float* s_f = (const float*)d_in[1];
    const float* s_y = (const float*)d_in[2];
    const float* P   = (const float*)d_in[3];
    const float* Wd  = (const float*)d_in[4];
    const float* bd  = (const float*)d_in[5];
    const float* Wu  = (const float*)d_in[6];
    const float* bu  = (const float*)d_in[7];
    float* out = (float*)d_out;

    static bool attr_set = false;
    if (!attr_set) {
        cudaFuncSetAttribute(fused_k, cudaFuncAttributeMaxDynamicSharedMemorySize, SM_BYTES);
        attr_set = true;
    }

    prep0_k<<<512, 256>>>(Wd, Wu);
    proto_sum_k<<<dim3(20, 8), 256>>>(s_f, s_y);
    select2_k<<<8, 256>>>(P);
    fused_k<<<313, 256, SM_BYTES>>>(x, s_f, bd, bu, out);
}

// round 10
// speedup vs baseline: 1.8338x; 1.0467x over previous
#include <cuda_runtime.h>
#include <cuda_fp16.h>
#include <cstdint>

#define ROWS_TOT 40000
#define ROWS_SF  20000

// ---------------- scratch (static device globals; no runtime allocation) ----------------
__device__ float g_psum[8 * 1024];
__device__ float g_cnt[8];
__device__ float g_pvec[8 * 1024];
__device__ __align__(16) __half g_wd_hi[16 * 64 * 64];   // [chunk][n][k] fp16
__device__ __align__(16) __half g_wd_lo[16 * 64 * 64];
__device__ __align__(16) __half g_wu_hi[1024 * 64];      // [n][k] fp16 (chunk = n/64)
__device__ __align__(16) __half g_wu_lo[1024 * 64];

// ---------------- helpers ----------------
__device__ __forceinline__ void mma_f16(float* d, uint32_t a0, uint32_t a1, uint32_t a2,
                                        uint32_t a3, uint32_t b0, uint32_t b1) {
    asm volatile(
        "mma.sync.aligned.m16n8k16.row.col.f32.f16.f16.f32 "
        "{%0,%1,%2,%3}, {%4,%5,%6,%7}, {%8,%9}, {%0,%1,%2,%3};"
        : "+f"(d[0]), "+f"(d[1]), "+f"(d[2]), "+f"(d[3])
        : "r"(a0), "r"(a1), "r"(a2), "r"(a3), "r"(b0), "r"(b1));
}
__device__ __forceinline__ void ldsm_x4(uint32_t addr, uint32_t* r) {
    asm volatile("ldmatrix.sync.aligned.m8n8.x4.shared.b16 {%0,%1,%2,%3}, [%4];"
                 : "=r"(r[0]), "=r"(r[1]), "=r"(r[2]), "=r"(r[3]) : "r"(addr));
}
__device__ __forceinline__ uint32_t smem_u32(const void* p) {
    uint32_t a;
    asm("{ .reg .u64 t; cvta.to.shared.u64 t, %1; cvt.u32.u64 %0, t; }" : "=r"(a) : "l"(p));
    return a;
}
__device__ __forceinline__ uint32_t pkh2(float x, float y) {
    __half2 h = __float22half2_rn(make_float2(x, y));
    return *reinterpret_cast<uint32_t*>(&h);
}
__device__ __forceinline__ void cpasync16(uint32_t saddr, const void* gaddr) {
    asm volatile("cp.async.cg.shared.global [%0], [%1], 16;" :: "r"(saddr), "l"(gaddr));
}
__device__ __forceinline__ void cp_commit() {
    asm volatile("cp.async.commit_group;");
}
__device__ __forceinline__ void cp_wait0() {
    asm volatile("cp.async.wait_group 0;");
}

// ---------------- K1: zero + weight prep (fp16 hi/lo) ----------------
__global__ void prep0_k(const float* __restrict__ Wd, const float* __restrict__ Wu) {
    int i = blockIdx.x * 256 + threadIdx.x;
    if (i < 8192) g_psum[i] = 0.0f;
    if (i < 8)    g_cnt[i]  = 0.0f;
    if (i < 65536) {                       // Wd [64][1024] -> chunked [16][64][64]
        int n = i >> 10, kk = i & 1023;
        int c = kk >> 6, k = kk & 63;
        float v = Wd[i];
        __half h = __float2half_rn(v);
        __half l = __float2half_rn(v - __half2float(h));
        int o = c * 4096 + n * 64 + k;
        g_wd_hi[o] = h; g_wd_lo[o] = l;
    } else if (i < 131072) {               // Wu [1024][64]
        int j = i - 65536;
        float v = Wu[j];
        __half h = __float2half_rn(v);
        __half l = __float2half_rn(v - __half2float(h));
        g_wu_hi[j] = h; g_wu_lo[j] = l;
    }
}

// ---------------- K2: masked prototype sum ----------------
__global__ void proto_sum_k(const float* __restrict__ s_f, const float* __restrict__ s_y) {
    const int b  = blockIdx.y;
    const int n0 = blockIdx.x * 125;
    const int t  = threadIdx.x;
    const float* sy = s_y + (size_t)b * 160000;
    float4 acc = make_float4(0.f, 0.f, 0.f, 0.f);
    int cnt = 0;
    for (int n = n0; n < n0 + 125; n++) {
        float m = sy[(n / 50) * 3200 + (n % 50) * 8];   // nearest-neighbor stride-8
        if (m == 1.0f) {
            float4 v = *(const float4*)(s_f + (size_t)(b * 2500 + n) * 1024 + t * 4);
            acc.x += v.x; acc.y += v.y; acc.z += v.z; acc.w += v.w;
            cnt++;
        }
    }
    float* ps = g_psum + b * 1024 + t * 4;
    atomicAdd(ps + 0, acc.x); atomicAdd(ps + 1, acc.y);
    atomicAdd(ps + 2, acc.z); atomicAdd(ps + 3, acc.w);
    if (t == 0) atomicAdd(&g_cnt[b], (float)cnt);
}

// ---------------- K3: prototype selection (grid 8 = one CTA per batch) ----------------
__global__ void select2_k(const float* __restrict__ P) {   // P: [1024][16]
    __shared__ float s_sim[16], s_n2[16];
    __shared__ int   ssel;
    __shared__ float sfac;
    const int b = blockIdx.x, t = threadIdx.x, lane = t & 31, w = t >> 5;
    const float* ps = g_psum + b * 1024;
    for (int c = w; c < 16; c += 8) {
        float sd = 0.f, sn = 0.f;
        for (int d = lane; d < 1024; d += 32) {
            float pv = P[d * 16 + c];
            sd = fmaf(ps[d], pv, sd);
            sn = fmaf(pv, pv, sn);
        }
        #pragma unroll
        for (int o = 16; o; o >>= 1) {
            sd += __shfl_xor_sync(0xFFFFFFFFu, sd, o);
            sn += __shfl_xor_sync(0xFFFFFFFFu, sn, o);
        }
        if (!lane) { s_sim[c] = sd; s_n2[c] = sn; }
    }
    __syncthreads();
    if (t == 0) {
        int best = 0; float bv = -1e30f;
        #pragma unroll
        for (int c = 0; c < 16; c++) {
            float v = s_sim[c] * rsqrtf(fmaxf(s_n2[c], 1e-24f));
            if (v > bv) { bv = v; best = c; }
        }
        ssel = best;
        float sign = (g_cnt[b] > 0.5f) ? 1.0f : 0.0f;
        sfac = sign * 32.0f * rsqrtf(fmaxf(s_n2[best], 1e-24f));
    }
    __syncthreads();
    const int sel = ssel; const float fac = sfac;
    #pragma unroll
    for (int i = 0; i < 4; i++) {
        int d = t + i * 256;
        g_pvec[b * 1024 + d] = P[d * 16 + sel] * fac;
    }
}

// ================= K4: fused enhance + down GEMM + up GEMM (fp16 HMMA) =================
// grid 313, BM=128. 256 thr = 8 warps (4 warpM x 2 warpN).
// Double-buffered smem, byte layout:
//   A0[0,18432) A1[18432,36864) Bh0[36864,46080) Bh1[46080,55296)
//   Bl0[55296,64512) Bl1[64512,73728) sA[73728,74240)
// (Bl plane = Bh plane + 18432 for the same buffer index.)
// Row stride 144 B => conflict-free stores and ldmatrix.
#define SM_BYTES 74240
extern __shared__ uint32_t smw[];

__global__ void __launch_bounds__(256, 2)
fused_k(const float* __restrict__ x, const float* __restrict__ s_f,
        const float* __restrict__ bdn, const float* __restrict__ bup,
        float* __restrict__ out) {
    uint32_t* Aw0 = smw;                       // A buffers (word offsets)
    float*    sA  = (float*)(smw + 18432);

    const uint32_t sbase = smem_u32(smw);
    const int t = threadIdx.x, wid = t >> 5, lane = t & 31;
    const int warpM = wid & 3, warpN = wid >> 2;
    const int row0 = blockIdx.x * 128;
    const int rl = t >> 1, half = t & 1;
    const int grow = row0 + rl;
    const bool rok = grow < ROWS_TOT;
    const float* src = rok ? ((grow < ROWS_SF) ? s_f + (size_t)grow * 1024
                                               : x + (size_t)(grow - ROWS_SF) * 1024)
                           : x;
    const int bb = rok ? ((grow < ROWS_SF) ? grow / 2500 : (grow - ROWS_SF) / 2500) : 0;
    const float* pvp = g_pvec + bb * 1024 + half * 32;

    // ldmatrix per-lane base addresses (byte), buffer 0
    const int lr16 = lane & 15, lk16 = (lane >> 4) & 1;
    const uint32_t aAddr0 = sbase + (uint32_t)((warpM * 32 + lr16) * 144 + lk16 * 16);
    const int br = warpN * 32 + ((lane >> 4) & 1) * 8 + (lane & 7);
    const uint32_t bhAddr0 = sbase + 36864 + (uint32_t)(br * 144 + ((lane >> 3) & 1) * 16);

    // cp.async B-tile segment (this thread handles 2 segments per plane)
    const int cn0 = t >> 3, cq0 = (t & 7);            // segment 0: n=cn0, q=cq0
    const int cn1 = (t + 256) >> 3, cq1 = cq0;        // segment 1
    const uint32_t bdst0 = sbase + 36864 + (uint32_t)(cn0 * 144 + cq0 * 16);
    const uint32_t bdst1 = sbase + 36864 + (uint32_t)(cn1 * 144 + cq1 * 16);
    const int bsrc0 = cn0 * 64 + cq0 * 8, bsrc1 = cn1 * 64 + cq1 * 8;

    float acc[8][4];
    #pragma unroll
    for (int i = 0; i < 8; i++)
        #pragma unroll
        for (int j = 0; j < 4; j++) acc[i][j] = 0.f;

    float sq = 0.f, dp = 0.f;
    float4 f[8];

    // ---- prologue: chunk 0 ----
    #pragma unroll
    for (int i = 0; i < 8; i++)
        f[i] = rok ? *(const float4*)(src + half * 32 + i * 4) : make_float4(0.f, 0.f, 0.f, 0.f);
    cpasync16(bdst0, g_wd_hi + bsrc0);
    cpasync16(bdst0 + 18432, g_wd_lo + bsrc0);
    cpasync16(bdst1, g_wd_hi + bsrc1);
    cpasync16(bdst1 + 18432, g_wd_lo + bsrc1);
    cp_commit();
    {   // convert + sq/dp + store chunk0 A into buffer 0
        int w0 = rl * 36 + half * 16;
        #pragma unroll
        for (int i = 0; i < 8; i += 2) {
            float4 p0 = *(const float4*)(pvp + i * 4);
            float4 p1 = *(const float4*)(pvp + i * 4 + 4);
            sq = fmaf(f[i].x, f[i].x, fmaf(f[i].y, f[i].y, fmaf(f[i].z, f[i].z, fmaf(f[i].w, f[i].w, sq))));
            dp = fmaf(f[i].x, p0.x, fmaf(f[i].y, p0.y, fmaf(f[i].z, p0.z, fmaf(f[i].w, p0.w, dp))));
            sq = fmaf(f[i+1].x, f[i+1].x, fmaf(f[i+1].y, f[i+1].y, fmaf(f[i+1].z, f[i+1].z, fmaf(f[i+1].w, f[i+1].w, sq))));
            dp = fmaf(f[i+1].x, p1.x, fmaf(f[i+1].y, p1.y, fmaf(f[i+1].z, p1.z, fmaf(f[i+1].w, p1.w, dp))));
            *(uint4*)(Aw0 + w0 + i * 2) = make_uint4(
                pkh2(f[i].x, f[i].y), pkh2(f[i].z, f[i].w),
                pkh2(f[i+1].x, f[i+1].y), pkh2(f[i+1].z, f[i+1].w));
        }
    }
    cp_wait0();
    __syncthreads();

    // ============ down phase: K=1024 in 16 chunks of 64, double-buffered ============
    #pragma unroll 1
    for (int c = 0; c < 16; c++) {
        const int cur = c & 1, nxt = cur ^ 1;
        if (c < 15) {
            // async B for next chunk into alternate buffer
            const __half* wh = g_wd_hi + (c + 1) * 4096;
            const __half* wl = g_wd_lo + (c + 1) * 4096;
            cpasync16(bdst0 + (uint32_t)nxt * 9216, wh + bsrc0);
            cpasync16(bdst0 + (uint32_t)nxt * 9216 + 18432, wl + bsrc0);
            cpasync16(bdst1 + (uint32_t)nxt * 9216, wh + bsrc1);
            cpasync16(bdst1 + (uint32_t)nxt * 9216 + 18432, wl + bsrc1);
            cp_commit();
            // LDG next A chunk (consumed after MMA block)
            const int kb = (c + 1) * 64 + half * 32;
            #pragma unroll
            for (int i = 0; i < 8; i++)
                f[i] = rok ? *(const float4*)(src + kb + i * 4) : make_float4(0.f, 0.f, 0.f, 0.f);
        }
        // MMA on current buffers
        {
            const uint32_t aA = aAddr0 + (uint32_t)cur * 18432;
            const uint32_t bhA = bhAddr0 + (uint32_t)cur * 9216;
            #pragma unroll
            for (int ks = 0; ks < 4; ks++) {
                uint32_t af[2][4], bh[2][4], bl[2][4];
                ldsm_x4(aA + ks * 32, af[0]);
                ldsm_x4(aA + 16 * 144 + ks * 32, af[1]);
                ldsm_x4(bhA + ks * 32, bh[0]);
                ldsm_x4(bhA + 16 * 144 + ks * 32, bh[1]);
                ldsm_x4(bhA + 18432 + ks * 32, bl[0]);
                ldsm_x4(bhA + 18432 + 16 * 144 + ks * 32, bl[1]);
                #pragma unroll
                for (int mt = 0; mt < 2; mt++)
                    #pragma unroll
                    for (int nt = 0; nt < 4; nt++) {
                        float* d = acc[mt * 4 + nt];
                        const int n2 = nt >> 1, s = (nt & 1) * 2;
                        mma_f16(d, af[mt][0], af[mt][1], af[mt][2], af[mt][3], bh[n2][s], bh[n2][s + 1]);
                        mma_f16(d, af[mt][0], af[mt][1], af[mt][2], af[mt][3], bl[n2][s], bl[n2][s + 1]);
                    }
            }
        }
        if (c < 15) {
            // convert + sq/dp + store next A into alternate buffer
            const float* pp = pvp + (c + 1) * 64;
            int w0 = nxt * 4608 + rl * 36 + half * 16;
            #pragma unroll
            for (int i = 0; i < 8; i += 2) {
                float4 p0 = *(const float4*)(pp + i * 4);
                float4 p1 = *(const float4*)(pp + i * 4 + 4);
                sq = fmaf(f[i].x, f[i].x, fmaf(f[i].y, f[i].y, fmaf(f[i].z, f[i].z, fmaf(f[i].w, f[i].w, sq))));
                dp = fmaf(f[i].x, p0.x, fmaf(f[i].y, p0.y, fmaf(f[i].z, p0.z, fmaf(f[i].w, p0.w, dp))));
                sq = fmaf(f[i+1].x, f[i+1].x, fmaf(f[i+1].y, f[i+1].y, fmaf(f[i+1].z, f[i+1].z, fmaf(f[i+1].w, f[i+1].w, sq))));
                dp = fmaf(f[i+1].x, p1.x, fmaf(f[i+1].y, p1.y, fmaf(f[i+1].z, p1.z, fmaf(f[i+1].w, p1.w, dp))));
                *(uint4*)(Aw0 + w0 + i * 2) = make_uint4(
                    pkh2(f[i].x, f[i].y), pkh2(f[i].z, f[i].w),
                    pkh2(f[i+1].x, f[i+1].y), pkh2(f[i+1].z, f[i+1].w));
            }
        }
        cp_wait0();
        __syncthreads();
    }

    // per-row enhancement scalar
    sq += __shfl_xor_sync(0xFFFFFFFFu, sq, 1);
    dp += __shfl_xor_sync(0xFFFFFFFFu, dp, 1);
    if (half == 0) {
        float g = fminf(fmaxf(dp / fmaxf(sqrtf(sq), 1e-12f), 0.0f), 6.0f);
        sA[rl] = 1.0f + g;
    }
    // prefetch up-phase chunk 0 B into buffer 0 (overlaps epilogue)
    cpasync16(bdst0, g_wu_hi + bsrc0);
    cpasync16(bdst0 + 18432, g_wu_lo + bsrc0);
    cpasync16(bdst1, g_wu_hi + bsrc1);
    cpasync16(bdst1 + 18432, g_wu_lo + bsrc1);
    cp_commit();
    __syncthreads();   // sA visible; all MMAs done (A buffers free)

    // ---- down epilogue: h = relu(a*dot + b_down) -> fp16 into A buffer 0 ----
    #pragma unroll
    for (int nt = 0; nt < 4; nt++) {
        const int c0 = warpN * 32 + nt * 8 + (lane & 3) * 2;
        const float bd0 = __ldg(bdn + c0), bd1 = __ldg(bdn + c0 + 1);
        #pragma unroll
        for (int mt = 0; mt < 2; mt++) {
            const float* d = acc[mt * 4 + nt];
            const int rb = warpM * 32 + mt * 16 + (lane >> 2);
            #pragma unroll
            for (int rr = 0; rr < 2; rr++) {
                const int rloc = rb + rr * 8;
                float av2 = sA[rloc];
                float h0 = fmaxf(fmaf(av2, d[rr * 2 + 0], bd0), 0.f);
                float h1 = fmaxf(fmaf(av2, d[rr * 2 + 1], bd1), 0.f);
                Aw0[rloc * 36 + c0 / 2] = pkh2(h0, h1);
            }
        }
    }
    cp_wait0();
    __syncthreads();   // h visible, B0 loaded

    // ============ up phase: 16 N-chunks of 64, A = h (buffer 0), B double-buffered ============
    #pragma unroll 1
    for (int nc = 0; nc < 16; nc++) {
        const int cur = nc & 1;
        if (nc < 15) {
            const __half* wh = g_wu_hi + (nc + 1) * 4096;
            const __half* wl = g_wu_lo + (nc + 1) * 4096;
            const uint32_t bo = (uint32_t)(cur ^ 1) * 9216;
            cpasync16(bdst0 + bo, wh + bsrc0);
            cpasync16(bdst0 + bo + 18432, wl + bsrc0);
            cpasync16(bdst1 + bo, wh + bsrc1);
            cpasync16(bdst1 + bo + 18432, wl + bsrc1);
            cp_commit();
        }
        #pragma unroll
        for (int i = 0; i < 8; i++)
            #pragma unroll
            for (int j = 0; j < 4; j++) acc[i][j] = 0.f;

        {
            const uint32_t bhA = bhAddr0 + (uint32_t)cur * 9216;
            #pragma unroll
            for (int ks = 0; ks < 4; ks++) {
                uint32_t af[2][4], bh[2][4], bl[2][4];
                ldsm_x4(aAddr0 + ks * 32, af[0]);
                ldsm_x4(aAddr0 + 16 * 144 + ks * 32, af[1]);
                ldsm_x4(bhA + ks * 32, bh[0]);
                ldsm_x4(bhA + 16 * 144 + ks * 32, bh[1]);
                ldsm_x4(bhA + 18432 + ks * 32, bl[0]);
                ldsm_x4(bhA + 18432 + 16 * 144 + ks * 32, bl[1]);
                #pragma unroll
                for (int mt = 0; mt < 2; mt++)
                    #pragma unroll
                    for (int nt = 0; nt < 4; nt++) {
                        float* d = acc[mt * 4 + nt];
                        const int n2 = nt >> 1, s = (nt & 1) * 2;
                        mma_f16(d, af[mt][0], af[mt][1], af[mt][2], af[mt][3], bh[n2][s], bh[n2][s + 1]);
                        mma_f16(d, af[mt][0], af[mt][1], af[mt][2], af[mt][3], bl[n2][s], bl[n2][s + 1]);
                    }
            }
        }

        // epilogue: out = acc + b_up
        const int nb64 = nc * 64;
        #pragma unroll
        for (int nt = 0; nt < 4; nt++) {
            const int c0 = warpN * 32 + nt * 8 + (lane & 3) * 2;
            const float u0 = __ldg(bup + nb64 + c0), u1 = __ldg(bup + nb64 + c0 + 1);
            #pragma unroll
            for (int mt = 0; mt < 2; mt++) {
                const float* d = acc[mt * 4 + nt];
                const int rb = warpM * 32 + mt * 16 + (lane >> 2);
                #pragma unroll
                for (int rr = 0; rr < 2; rr++) {
                    int row = row0 + rb + rr * 8;
                    if (row < ROWS_TOT) {
                        float2 v = make_float2(d[rr * 2 + 0] + u0, d[rr * 2 + 1] + u1);
                        *(float2*)(out + (size_t)row * 1024 + nb64 + c0) = v;
                    }
                }
            }
        }
        cp_wait0();
        __syncthreads();
    }
}

// ---------------- launch ----------------
extern "C" void kernel_launch(void* const* d_in, const int* in_sizes, int n_in,
                              void* d_out, int out_size) {
    (void)in_sizes; (void)n_in; (void)out_size;
    const float* x   = (const float*)d_in[0];
    const float* s_f = (const float*)d_in[1];
    const float* s_y = (const float*)d_in[2];
    const float* P   = (const float*)d_in[3];
    const float* Wd  = (const float*)d_in[4];
    const float* bd  = (const float*)d_in[5];
    const float* Wu  = (const float*)d_in[6];
    const float* bu  = (const float*)d_in[7];
    float* out = (float*)d_out;

    static bool attr_set = false;
    if (!attr_set) {
        cudaFuncSetAttribute(fused_k, cudaFuncAttributeMaxDynamicSharedMemorySize, SM_BYTES);
        attr_set = true;
    }

    prep0_k<<<512, 256>>>(Wd, Wu);
    proto_sum_k<<<dim3(20, 8), 256>>>(s_f, s_y);
    select2_k<<<8, 256>>>(P);
    fused_k<<<313, 256, SM_BYTES>>>(x, s_f, bd, bu, out);
}

// round 11
// speedup vs baseline: 2.4119x; 1.3153x over previous
#include <cuda_runtime.h>
#include <cuda_fp16.h>
#include <cstdint>

#define ROWS_TOT 40000
#define ROWS_SF  20000
#define ROWS_PAD 40064        // 313 * 128

// ---------------- scratch (static device globals; no runtime allocation) ----------------
__device__ float g_psum[8 * 1024];
__device__ float g_cnt[8];
__device__ float g_pvec[8 * 1024];
__device__ float g_a[ROWS_PAD];
__device__ __align__(16) __half g_fh[(size_t)ROWS_PAD * 1024];   // pre-converted features
__device__ __align__(16) __half g_wd[16 * 64 * 64];   // [chunk][n][k] fp16
__device__ __align__(16) __half g_wu[1024 * 64];      // [n][k] fp16 (chunk = n/64)

// ---------------- helpers ----------------
__device__ __forceinline__ void mma_f16(float* d, uint32_t a0, uint32_t a1, uint32_t a2,
                                        uint32_t a3, uint32_t b0, uint32_t b1) {
    asm volatile(
        "mma.sync.aligned.m16n8k16.row.col.f32.f16.f16.f32 "
        "{%0,%1,%2,%3}, {%4,%5,%6,%7}, {%8,%9}, {%0,%1,%2,%3};"
        : "+f"(d[0]), "+f"(d[1]), "+f"(d[2]), "+f"(d[3])
        : "r"(a0), "r"(a1), "r"(a2), "r"(a3), "r"(b0), "r"(b1));
}
__device__ __forceinline__ void ldsm_x4(uint32_t addr, uint32_t* r) {
    asm volatile("ldmatrix.sync.aligned.m8n8.x4.shared.b16 {%0,%1,%2,%3}, [%4];"
                 : "=r"(r[0]), "=r"(r[1]), "=r"(r[2]), "=r"(r[3]) : "r"(addr));
}
__device__ __forceinline__ uint32_t smem_u32(const void* p) {
    uint32_t a;
    asm("{ .reg .u64 t; cvta.to.shared.u64 t, %1; cvt.u32.u64 %0, t; }" : "=r"(a) : "l"(p));
    return a;
}
__device__ __forceinline__ uint32_t pkh2(float x, float y) {
    __half2 h = __float22half2_rn(make_float2(x, y));
    return *reinterpret_cast<uint32_t*>(&h);
}
__device__ __forceinline__ void cpasync16(uint32_t saddr, const void* gaddr) {
    asm volatile("cp.async.cg.shared.global [%0], [%1], 16;" :: "r"(saddr), "l"(gaddr));
}
__device__ __forceinline__ void cp_commit() {
    asm volatile("cp.async.commit_group;");
}
__device__ __forceinline__ void cp_wait0() {
    asm volatile("cp.async.wait_group 0;");
}

// ---------------- K1: zero + weight prep (fp16) ----------------
__global__ void prep0_k(const float* __restrict__ Wd, const float* __restrict__ Wu) {
    int i = blockIdx.x * 256 + threadIdx.x;
    if (i < 8192) g_psum[i] = 0.0f;
    if (i < 8)    g_cnt[i]  = 0.0f;
    if (i < 65536) {                       // Wd [64][1024] -> chunked [16][64][64]
        int n = i >> 10, kk = i & 1023;
        int c = kk >> 6, k = kk & 63;
        g_wd[c * 4096 + n * 64 + k] = __float2half_rn(Wd[i]);
    } else if (i < 131072) {               // Wu [1024][64]
        int j = i - 65536;
        g_wu[j] = __float2half_rn(Wu[j]);
    }
}

// ---------------- K2: masked prototype sum ----------------
__global__ void proto_sum_k(const float* __restrict__ s_f, const float* __restrict__ s_y) {
    const int b  = blockIdx.y;
    const int n0 = blockIdx.x * 125;
    const int t  = threadIdx.x;
    const float* sy = s_y + (size_t)b * 160000;
    float4 acc = make_float4(0.f, 0.f, 0.f, 0.f);
    int cnt = 0;
    for (int n = n0; n < n0 + 125; n++) {
        float m = sy[(n / 50) * 3200 + (n % 50) * 8];   // nearest-neighbor stride-8
        if (m == 1.0f) {
            float4 v = *(const float4*)(s_f + (size_t)(b * 2500 + n) * 1024 + t * 4);
            acc.x += v.x; acc.y += v.y; acc.z += v.z; acc.w += v.w;
            cnt++;
        }
    }
    float* ps = g_psum + b * 1024 + t * 4;
    atomicAdd(ps + 0, acc.x); atomicAdd(ps + 1, acc.y);
    atomicAdd(ps + 2, acc.z); atomicAdd(ps + 3, acc.w);
    if (t == 0) atomicAdd(&g_cnt[b], (float)cnt);
}

// ---------------- K3: prototype selection (grid 8 = one CTA per batch) ----------------
__global__ void select2_k(const float* __restrict__ P) {   // P: [1024][16]
    __shared__ float s_sim[16], s_n2[16];
    __shared__ int   ssel;
    __shared__ float sfac;
    const int b = blockIdx.x, t = threadIdx.x, lane = t & 31, w = t >> 5;
    const float* ps = g_psum + b * 1024;
    for (int c = w; c < 16; c += 8) {
        float sd = 0.f, sn = 0.f;
        for (int d = lane; d < 1024; d += 32) {
            float pv = P[d * 16 + c];
            sd = fmaf(ps[d], pv, sd);
            sn = fmaf(pv, pv, sn);
        }
        #pragma unroll
        for (int o = 16; o; o >>= 1) {
            sd += __shfl_xor_sync(0xFFFFFFFFu, sd, o);
            sn += __shfl_xor_sync(0xFFFFFFFFu, sn, o);
        }
        if (!lane) { s_sim[c] = sd; s_n2[c] = sn; }
    }
    __syncthreads();
    if (t == 0) {
        int best = 0; float bv = -1e30f;
        #pragma unroll
        for (int c = 0; c < 16; c++) {
            float v = s_sim[c] * rsqrtf(fmaxf(s_n2[c], 1e-24f));
            if (v > bv) { bv = v; best = c; }
        }
        ssel = best;
        float sign = (g_cnt[b] > 0.5f) ? 1.0f : 0.0f;
        sfac = sign * 32.0f * rsqrtf(fmaxf(s_n2[best], 1e-24f));
    }
    __syncthreads();
    const int sel = ssel; const float fac = sfac;
    #pragma unroll
    for (int i = 0; i < 4; i++) {
        int d = t + i * 256;
        g_pvec[b * 1024 + d] = P[d * 16 + sel] * fac;
    }
}

// ---------------- K4: convert features to fp16 + per-row enhance scalar ----------------
// warp per row, grid 5008 (40064 rows).
__global__ void convert_k(const float* __restrict__ x, const float* __restrict__ s_f) {
    const int r = blockIdx.x * 8 + (threadIdx.x >> 5);
    const int lane = threadIdx.x & 31;
    __half* dst = g_fh + (size_t)r * 1024;
    if (r < ROWS_TOT) {
        const float* src = (r < ROWS_SF) ? s_f + (size_t)r * 1024
                                         : x + (size_t)(r - ROWS_SF) * 1024;
        const int bb = (r < ROWS_SF) ? r / 2500 : (r - ROWS_SF) / 2500;
        const float* pv = g_pvec + bb * 1024;
        float sq = 0.f, dp = 0.f;
        #pragma unroll
        for (int i = 0; i < 8; i++) {
            int c = i * 128 + lane * 4;
            float4 f = *(const float4*)(src + c);
            float4 p = *(const float4*)(pv + c);
            sq = fmaf(f.x, f.x, fmaf(f.y, f.y, fmaf(f.z, f.z, fmaf(f.w, f.w, sq))));
            dp = fmaf(f.x, p.x, fmaf(f.y, p.y, fmaf(f.z, p.z, fmaf(f.w, p.w, dp))));
            *(uint2*)(dst + c) = make_uint2(pkh2(f.x, f.y), pkh2(f.z, f.w));
        }
        #pragma unroll
        for (int o = 16; o; o >>= 1) {
            sq += __shfl_xor_sync(0xFFFFFFFFu, sq, o);
            dp += __shfl_xor_sync(0xFFFFFFFFu, dp, o);
        }
        if (!lane) {
            float g = fminf(fmaxf(dp / fmaxf(sqrtf(sq), 1e-12f), 0.0f), 6.0f);
            g_a[r] = 1.0f + g;
        }
    } else {
        #pragma unroll
        for (int i = 0; i < 8; i++)
            *(uint2*)(dst + i * 128 + lane * 4) = make_uint2(0u, 0u);
        if (!lane) g_a[r] = 1.0f;
    }
}

// ================= K5: fused down GEMM + up GEMM (fp16 HMMA, all cp.async) =================
// grid 313, BM=128. 256 thr = 8 warps (4 warpM x 2 warpN). Occupancy 3.
// smem byte layout (double buffered):
//   A0[0,18432) A1[18432,36864) B0[36864,46080) B1[46080,55296) sA[55296,55808)
// Row stride 144 B => conflict-free stores and ldmatrix.
#define SM_BYTES 55808
extern __shared__ uint32_t smw[];

__global__ void __launch_bounds__(256, 3)
fused2_k(const float* __restrict__ bdn, const float* __restrict__ bup,
         float* __restrict__ out) {
    uint32_t* Aw0 = smw;
    float*    sA  = (float*)(smw + 13824);

    const uint32_t sbase = smem_u32(smw);
    const int t = threadIdx.x, wid = t >> 5, lane = t & 31;
    const int warpM = wid & 3, warpN = wid >> 2;
    const int row0 = blockIdx.x * 128;

    // ldmatrix per-lane base addresses (byte), stage 0
    const int lr16 = lane & 15, lk16 = (lane >> 4) & 1;
    const uint32_t aAddr0 = sbase + (uint32_t)((warpM * 32 + lr16) * 144 + lk16 * 16);
    const int brr = warpN * 32 + ((lane >> 4) & 1) * 8 + (lane & 7);
    const uint32_t bAddr0 = sbase + 36864 + (uint32_t)(brr * 144 + ((lane >> 3) & 1) * 16);

    // cp.async segment mapping
    //  A: 1024 segs (128 rows x 8), 4 per thread;  B: 512 segs (64 n x 8), 2 per thread
    const int an0 = t >> 3, aq = t & 7;     // A segs j: row = an0 + j*32
    const uint32_t adst = sbase + (uint32_t)(an0 * 144 + aq * 16);
    const int bn0 = t >> 3;                  // B segs j: n = bn0 + j*32
    const uint32_t bdst = sbase + 36864 + (uint32_t)(bn0 * 144 + aq * 16);
    const __half* asrc = g_fh + (size_t)(row0 + an0) * 1024 + aq * 8;

    if (t < 128) sA[t] = g_a[row0 + t];

    float acc[8][4];
    #pragma unroll
    for (int i = 0; i < 8; i++)
        #pragma unroll
        for (int j = 0; j < 4; j++) acc[i][j] = 0.f;

    // ---- prologue: chunk 0 into stage 0 ----
    #pragma unroll
    for (int j = 0; j < 4; j++)
        cpasync16(adst + (uint32_t)(j * 32) * 144, asrc + (size_t)(j * 32) * 1024);
    #pragma unroll
    for (int j = 0; j < 2; j++)
        cpasync16(bdst + (uint32_t)(j * 32) * 144, g_wd + (bn0 + j * 32) * 64 + aq * 8);
    cp_commit();
    cp_wait0();
    __syncthreads();

    // ============ down phase: 16 chunks of 64, double-buffered ============
    #pragma unroll 1
    for (int c = 0; c < 16; c++) {
        const uint32_t cur = (uint32_t)(c & 1), nxt = cur ^ 1u;
        if (c < 15) {
            const __half* as = asrc + (c + 1) * 64;
            const __half* bs = g_wd + (c + 1) * 4096 + bn0 * 64 + aq * 8;
            #pragma unroll
            for (int j = 0; j < 4; j++)
                cpasync16(adst + nxt * 18432u + (uint32_t)(j * 32) * 144, as + (size_t)(j * 32) * 1024);
            #pragma unroll
            for (int j = 0; j < 2; j++)
                cpasync16(bdst + nxt * 9216u + (uint32_t)(j * 32) * 144, bs + j * 32 * 64);
            cp_commit();
        }
        {
            const uint32_t aA = aAddr0 + cur * 18432u;
            const uint32_t bA = bAddr0 + cur * 9216u;
            #pragma unroll
            for (int ks = 0; ks < 4; ks++) {
                uint32_t af[2][4], bf[2][4];
                ldsm_x4(aA + ks * 32, af[0]);
                ldsm_x4(aA + 16 * 144 + ks * 32, af[1]);
                ldsm_x4(bA + ks * 32, bf[0]);
                ldsm_x4(bA + 16 * 144 + ks * 32, bf[1]);
                #pragma unroll
                for (int mt = 0; mt < 2; mt++)
                    #pragma unroll
                    for (int nt = 0; nt < 4; nt++) {
                        const int n2 = nt >> 1, s = (nt & 1) * 2;
                        mma_f16(acc[mt * 4 + nt], af[mt][0], af[mt][1], af[mt][2], af[mt][3],
                                bf[n2][s], bf[n2][s + 1]);
                    }
            }
        }
        cp_wait0();
        __syncthreads();
    }

    // prefetch up-phase chunk 0 B into stage 0 (B planes free)
    #pragma unroll
    for (int j = 0; j < 2; j++)
        cpasync16(bdst + (uint32_t)(j * 32) * 144, g_wu + (bn0 + j * 32) * 64 + aq * 8);
    cp_commit();

    // ---- down epilogue: h = relu(a*dot + b_down) -> fp16 into A stage-0 plane ----
    #pragma unroll
    for (int nt = 0; nt < 4; nt++) {
        const int c0 = warpN * 32 + nt * 8 + (lane & 3) * 2;
        const float bd0 = __ldg(bdn + c0), bd1 = __ldg(bdn + c0 + 1);
        #pragma unroll
        for (int mt = 0; mt < 2; mt++) {
            const float* d = acc[mt * 4 + nt];
            const int rb = warpM * 32 + mt * 16 + (lane >> 2);
            #pragma unroll
            for (int rr = 0; rr < 2; rr++) {
                const int rloc = rb + rr * 8;
                float av2 = sA[rloc];
                float h0 = fmaxf(fmaf(av2, d[rr * 2 + 0], bd0), 0.f);
                float h1 = fmaxf(fmaf(av2, d[rr * 2 + 1], bd1), 0.f);
                Aw0[rloc * 36 + c0 / 2] = pkh2(h0, h1);
            }
        }
    }
    cp_wait0();
    __syncthreads();   // h visible, up-B0 loaded

    // ============ up phase: 16 N-chunks of 64, A = h (stage 0), B double-buffered ============
    #pragma unroll 1
    for (int nc = 0; nc < 16; nc++) {
        const uint32_t cur = (uint32_t)(nc & 1);
        if (nc < 15) {
            const __half* bs = g_wu + (nc + 1) * 4096 + bn0 * 64 + aq * 8;
            const uint32_t bo = (cur ^ 1u) * 9216u;
            #pragma unroll
            for (int j = 0; j < 2; j++)
                cpasync16(bdst + bo + (uint32_t)(j * 32) * 144, bs + j * 32 * 64);
            cp_commit();
        }
        #pragma unroll
        for (int i = 0; i < 8; i++)
            #pragma unroll
            for (int j = 0; j < 4; j++) acc[i][j] = 0.f;
        {
            const uint32_t bA = bAddr0 + cur * 9216u;
            #pragma unroll
            for (int ks = 0; ks < 4; ks++) {
                uint32_t af[2][4], bf[2][4];
                ldsm_x4(aAddr0 + ks * 32, af[0]);
                ldsm_x4(aAddr0 + 16 * 144 + ks * 32, af[1]);
                ldsm_x4(bA + ks * 32, bf[0]);
                ldsm_x4(bA + 16 * 144 + ks * 32, bf[1]);
                #pragma unroll
                for (int mt = 0; mt < 2; mt++)
                    #pragma unroll
                    for (int nt = 0; nt < 4; nt++) {
                        const int n2 = nt >> 1, s = (nt & 1) * 2;
                        mma_f16(acc[mt * 4 + nt], af[mt][0], af[mt][1], af[mt][2], af[mt][3],
                                bf[n2][s], bf[n2][s + 1]);
                    }
            }
        }
        // epilogue: out = acc + b_up
        const int nb64 = nc * 64;
        #pragma unroll
        for (int nt = 0; nt < 4; nt++) {
            const int c0 = warpN * 32 + nt * 8 + (lane & 3) * 2;
            const float u0 = __ldg(bup + nb64 + c0), u1 = __ldg(bup + nb64 + c0 + 1);
            #pragma unroll
            for (int mt = 0; mt < 2; mt++) {
                const float* d = acc[mt * 4 + nt];
                const int rb = warpM * 32 + mt * 16 + (lane >> 2);
                #pragma unroll
                for (int rr = 0; rr < 2; rr++) {
                    int row = row0 + rb + rr * 8;
                    if (row < ROWS_TOT) {
                        float2 v = make_float2(d[rr * 2 + 0] + u0, d[rr * 2 + 1] + u1);
                        *(float2*)(out + (size_t)row * 1024 + nb64 + c0) = v;
                    }
                }
            }
        }
        cp_wait0();
        __syncthreads();
    }
}

// ---------------- launch ----------------
extern "C" void kernel_launch(void* const* d_in, const int* in_sizes, int n_in,
                              void* d_out, int out_size) {
    (void)in_sizes; (void)n_in; (void)out_size;
    const float* x   = (const float*)d_in[0];
    const float* s_f = (const float*)d_in[1];
    const float* s_y = (const float*)d_in[2];
    const float* P   = (const float*)d_in[3];
    const float* Wd  = (const float*)d_in[4];
    const float* bd  = (const float*)d_in[5];
    const float* Wu  = (const float*)d_in[6];
    const float* bu  = (const float*)d_in[7];
    float* out = (float*)d_out;

    static bool attr_set = false;
    if (!attr_set) {
        cudaFuncSetAttribute(fused2_k, cudaFuncAttributeMaxDynamicSharedMemorySize, SM_BYTES);
        attr_set = true;
    }

    prep0_k<<<512, 256>>>(Wd, Wu);
    proto_sum_k<<<dim3(20, 8), 256>>>(s_f, s_y);
    select2_k<<<8, 256>>>(P);
    convert_k<<<5008, 256>>>(x, s_f);
    fused2_k<<<313, 256, SM_BYTES>>>(bd, bu, out);
}

// round 12
// speedup vs baseline: 2.4438x; 1.0132x over previous
#include <cuda_runtime.h>
#include <cuda_fp16.h>
#include <cstdint>

#define ROWS_TOT 40000
#define ROWS_SF  20000
#define ROWS_PAD 40064        // 313 * 128

// ---------------- scratch (static device globals; no runtime allocation) ----------------
__device__ float g_psum_p[160 * 1024];     // per-(batch,chunk) partial sums, no zeroing needed
__device__ float g_cnt_p[160];
__device__ float g_pvec[8 * 1024];
__device__ float g_a[ROWS_PAD];
__device__ __align__(16) __half g_fh[(size_t)ROWS_PAD * 1024];   // pre-converted features
__device__ __align__(16) __half g_wd[16 * 64 * 64];   // [chunk][n][k] fp16
__device__ __align__(16) __half g_wu[1024 * 64];      // [n][k] fp16 (chunk = n/64)

// ---------------- helpers ----------------
__device__ __forceinline__ void mma_f16(float* d, uint32_t a0, uint32_t a1, uint32_t a2,
                                        uint32_t a3, uint32_t b0, uint32_t b1) {
    asm volatile(
        "mma.sync.aligned.m16n8k16.row.col.f32.f16.f16.f32 "
        "{%0,%1,%2,%3}, {%4,%5,%6,%7}, {%8,%9}, {%0,%1,%2,%3};"
        : "+f"(d[0]), "+f"(d[1]), "+f"(d[2]), "+f"(d[3])
        : "r"(a0), "r"(a1), "r"(a2), "r"(a3), "r"(b0), "r"(b1));
}
__device__ __forceinline__ void ldsm_x4(uint32_t addr, uint32_t* r) {
    asm volatile("ldmatrix.sync.aligned.m8n8.x4.shared.b16 {%0,%1,%2,%3}, [%4];"
                 : "=r"(r[0]), "=r"(r[1]), "=r"(r[2]), "=r"(r[3]) : "r"(addr));
}
__device__ __forceinline__ uint32_t smem_u32(const void* p) {
    uint32_t a;
    asm("{ .reg .u64 t; cvta.to.shared.u64 t, %1; cvt.u32.u64 %0, t; }" : "=r"(a) : "l"(p));
    return a;
}
__device__ __forceinline__ uint32_t pkh2(float x, float y) {
    __half2 h = __float22half2_rn(make_float2(x, y));
    return *reinterpret_cast<uint32_t*>(&h);
}
__device__ __forceinline__ void cpasync16(uint32_t saddr, const void* gaddr) {
    asm volatile("cp.async.cg.shared.global [%0], [%1], 16;" :: "r"(saddr), "l"(gaddr));
}
__device__ __forceinline__ void cp_commit() {
    asm volatile("cp.async.commit_group;");
}
__device__ __forceinline__ void cp_wait0() {
    asm volatile("cp.async.wait_group 0;");
}

// ---------------- K1: weight prep + masked proto partial sums (fused, no zeroing) ---------
// grid 672: blocks [0,512) convert weights; blocks [512,672) do proto partials.
__global__ void prep_all_k(const float* __restrict__ Wd, const float* __restrict__ Wu,
                           const float* __restrict__ s_f, const float* __restrict__ s_y) {
    const int bid = blockIdx.x, t = threadIdx.x;
    if (bid < 512) {
        int i = bid * 256 + t;
        if (i < 65536) {                       // Wd [64][1024] -> chunked [16][64][64]
            int n = i >> 10, kk = i & 1023;
            int c = kk >> 6, k = kk & 63;
            g_wd[c * 4096 + n * 64 + k] = __float2half_rn(Wd[i]);
        } else {                               // Wu [1024][64]
            int j = i - 65536;
            g_wu[j] = __float2half_rn(Wu[j]);
        }
        return;
    }
    const int p = bid - 512;                   // 0..159
    const int b = p / 20, chunk = p % 20;
    const int n0 = chunk * 125;
    const float* sy = s_y + (size_t)b * 160000;
    float4 acc = make_float4(0.f, 0.f, 0.f, 0.f);
    int cnt = 0;
    for (int n = n0; n < n0 + 125; n++) {
        float m = sy[(n / 50) * 3200 + (n % 50) * 8];   // nearest-neighbor stride-8
        if (m == 1.0f) {
            float4 v = *(const float4*)(s_f + (size_t)(b * 2500 + n) * 1024 + t * 4);
            acc.x += v.x; acc.y += v.y; acc.z += v.z; acc.w += v.w;
            cnt++;
        }
    }
    *(float4*)(g_psum_p + (size_t)p * 1024 + t * 4) = acc;
    if (t == 0) g_cnt_p[p] = (float)cnt;
}

// ---------------- K2: prototype selection (grid 8 = one CTA per batch) ----------------
__global__ void select3_k(const float* __restrict__ P) {   // P: [1024][16]
    __shared__ float psum[1024];
    __shared__ float s_sim[16], s_n2[16];
    __shared__ float scnt;
    __shared__ int   ssel;
    __shared__ float sfac;
    const int b = blockIdx.x, t = threadIdx.x, lane = t & 31, w = t >> 5;
    #pragma unroll
    for (int i = 0; i < 4; i++) {
        int d = t + i * 256;
        float s = 0.f;
        #pragma unroll
        for (int p = 0; p < 20; p++) s += g_psum_p[(size_t)(b * 20 + p) * 1024 + d];
        psum[d] = s;
    }
    if (t == 0) {
        float c = 0.f;
        #pragma unroll
        for (int p = 0; p < 20; p++) c += g_cnt_p[b * 20 + p];
        scnt = c;
    }
    __syncthreads();
    for (int c = w; c < 16; c += 8) {
        float sd = 0.f, sn = 0.f;
        for (int d = lane; d < 1024; d += 32) {
            float pv = P[d * 16 + c];
            sd = fmaf(psum[d], pv, sd);
            sn = fmaf(pv, pv, sn);
        }
        #pragma unroll
        for (int o = 16; o; o >>= 1) {
            sd += __shfl_xor_sync(0xFFFFFFFFu, sd, o);
            sn += __shfl_xor_sync(0xFFFFFFFFu, sn, o);
        }
        if (!lane) { s_sim[c] = sd; s_n2[c] = sn; }
    }
    __syncthreads();
    if (t == 0) {
        int best = 0; float bv = -1e30f;
        #pragma unroll
        for (int c = 0; c < 16; c++) {
            float v = s_sim[c] * rsqrtf(fmaxf(s_n2[c], 1e-24f));
            if (v > bv) { bv = v; best = c; }
        }
        ssel = best;
        float sign = (scnt > 0.5f) ? 1.0f : 0.0f;
        sfac = sign * 32.0f * rsqrtf(fmaxf(s_n2[best], 1e-24f));
    }
    __syncthreads();
    const int sel = ssel; const float fac = sfac;
    #pragma unroll
    for (int i = 0; i < 4; i++) {
        int d = t + i * 256;
        g_pvec[b * 1024 + d] = P[d * 16 + sel] * fac;
    }
}

// ---------------- K3: convert features to fp16 + per-row enhance scalar ----------------
// warp per row, grid 5008 (40064 rows).
__global__ void convert_k(const float* __restrict__ x, const float* __restrict__ s_f) {
    const int r = blockIdx.x * 8 + (threadIdx.x >> 5);
    const int lane = threadIdx.x & 31;
    __half* dst = g_fh + (size_t)r * 1024;
    if (r < ROWS_TOT) {
        const float* src = (r < ROWS_SF) ? s_f + (size_t)r * 1024
                                         : x + (size_t)(r - ROWS_SF) * 1024;
        const int bb = (r < ROWS_SF) ? r / 2500 : (r - ROWS_SF) / 2500;
        const float* pv = g_pvec + bb * 1024;
        float sq = 0.f, dp = 0.f;
        #pragma unroll
        for (int i = 0; i < 8; i++) {
            int c = i * 128 + lane * 4;
            float4 f = *(const float4*)(src + c);
            float4 p = *(const float4*)(pv + c);
            sq = fmaf(f.x, f.x, fmaf(f.y, f.y, fmaf(f.z, f.z, fmaf(f.w, f.w, sq))));
            dp = fmaf(f.x, p.x, fmaf(f.y, p.y, fmaf(f.z, p.z, fmaf(f.w, p.w, dp))));
            *(uint2*)(dst + c) = make_uint2(pkh2(f.x, f.y), pkh2(f.z, f.w));
        }
        #pragma unroll
        for (int o = 16; o; o >>= 1) {
            sq += __shfl_xor_sync(0xFFFFFFFFu, sq, o);
            dp += __shfl_xor_sync(0xFFFFFFFFu, dp, o);
        }
        if (!lane) {
            float g = fminf(fmaxf(dp / fmaxf(sqrtf(sq), 1e-12f), 0.0f), 6.0f);
            g_a[r] = 1.0f + g;
        }
    } else {
        #pragma unroll
        for (int i = 0; i < 8; i++)
            *(uint2*)(dst + i * 128 + lane * 4) = make_uint2(0u, 0u);
        if (!lane) g_a[r] = 1.0f;
    }
}

// ================= K4: fused down GEMM + up GEMM (fp16 HMMA, all cp.async) =================
// grid 313, BM=128. 256 thr = 8 warps (4 warpM x 2 warpN). Occupancy 3.
// smem byte layout (double buffered):
//   A0[0,18432) A1[18432,36864) B0[36864,46080) B1[46080,55296) sA[55296,55808)
// Row stride 144 B => conflict-free stores and ldmatrix.
#define SM_BYTES 55808
extern __shared__ uint32_t smw[];

__global__ void __launch_bounds__(256, 3)
fused2_k(const float* __restrict__ bdn, const float* __restrict__ bup,
         float* __restrict__ out) {
    uint32_t* Aw0 = smw;
    float*    sA  = (float*)(smw + 13824);

    const uint32_t sbase = smem_u32(smw);
    const int t = threadIdx.x, wid = t >> 5, lane = t & 31;
    const int warpM = wid & 3, warpN = wid >> 2;
    const int row0 = blockIdx.x * 128;

    // ldmatrix per-lane base addresses (byte), stage 0
    const int lr16 = lane & 15, lk16 = (lane >> 4) & 1;
    const uint32_t aAddr0 = sbase + (uint32_t)((warpM * 32 + lr16) * 144 + lk16 * 16);
    const int brr = warpN * 32 + ((lane >> 4) & 1) * 8 + (lane & 7);
    const uint32_t bAddr0 = sbase + 36864 + (uint32_t)(brr * 144 + ((lane >> 3) & 1) * 16);

    // cp.async segment mapping
    const int an0 = t >> 3, aq = t & 7;
    const uint32_t adst = sbase + (uint32_t)(an0 * 144 + aq * 16);
    const int bn0 = t >> 3;
    const uint32_t bdst = sbase + 36864 + (uint32_t)(bn0 * 144 + aq * 16);
    const __half* asrc = g_fh + (size_t)(row0 + an0) * 1024 + aq * 8;

    if (t < 128) sA[t] = g_a[row0 + t];

    float acc[8][4];
    #pragma unroll
    for (int i = 0; i < 8; i++)
        #pragma unroll
        for (int j = 0; j < 4; j++) acc[i][j] = 0.f;

    // ---- prologue: chunk 0 into stage 0 ----
    #pragma unroll
    for (int j = 0; j < 4; j++)
        cpasync16(adst + (uint32_t)(j * 32) * 144, asrc + (size_t)(j * 32) * 1024);
    #pragma unroll
    for (int j = 0; j < 2; j++)
        cpasync16(bdst + (uint32_t)(j * 32) * 144, g_wd + (bn0 + j * 32) * 64 + aq * 8);
    cp_commit();
    cp_wait0();
    __syncthreads();

    // ============ down phase: 16 chunks of 64, double-buffered ============
    #pragma unroll 1
    for (int c = 0; c < 16; c++) {
        const uint32_t cur = (uint32_t)(c & 1), nxt = cur ^ 1u;
        if (c < 15) {
            const __half* as = asrc + (c + 1) * 64;
            const __half* bs = g_wd + (c + 1) * 4096 + bn0 * 64 + aq * 8;
            #pragma unroll
            for (int j = 0; j < 4; j++)
                cpasync16(adst + nxt * 18432u + (uint32_t)(j * 32) * 144, as + (size_t)(j * 32) * 1024);
            #pragma unroll
            for (int j = 0; j < 2; j++)
                cpasync16(bdst + nxt * 9216u + (uint32_t)(j * 32) * 144, bs + j * 32 * 64);
            cp_commit();
        }
        {
            const uint32_t aA = aAddr0 + cur * 18432u;
            const uint32_t bA = bAddr0 + cur * 9216u;
            #pragma unroll
            for (int ks = 0; ks < 4; ks++) {
                uint32_t af[2][4], bf[2][4];
                ldsm_x4(aA + ks * 32, af[0]);
                ldsm_x4(aA + 16 * 144 + ks * 32, af[1]);
                ldsm_x4(bA + ks * 32, bf[0]);
                ldsm_x4(bA + 16 * 144 + ks * 32, bf[1]);
                #pragma unroll
                for (int mt = 0; mt < 2; mt++)
                    #pragma unroll
                    for (int nt = 0; nt < 4; nt++) {
                        const int n2 = nt >> 1, s = (nt & 1) * 2;
                        mma_f16(acc[mt * 4 + nt], af[mt][0], af[mt][1], af[mt][2], af[mt][3],
                                bf[n2][s], bf[n2][s + 1]);
                    }
            }
        }
        cp_wait0();
        __syncthreads();
    }

    // prefetch up-phase chunk 0 B into stage 0 (B planes free)
    #pragma unroll
    for (int j = 0; j < 2; j++)
        cpasync16(bdst + (uint32_t)(j * 32) * 144, g_wu + (bn0 + j * 32) * 64 + aq * 8);
    cp_commit();

    // ---- down epilogue: h = relu(a*dot + b_down) -> fp16 into A stage-0 plane ----
    #pragma unroll
    for (int nt = 0; nt < 4; nt++) {
        const int c0 = warpN * 32 + nt * 8 + (lane & 3) * 2;
        const float bd0 = __ldg(bdn + c0), bd1 = __ldg(bdn + c0 + 1);
        #pragma unroll
        for (int mt = 0; mt < 2; mt++) {
            const float* d = acc[mt * 4 + nt];
            const int rb = warpM * 32 + mt * 16 + (lane >> 2);
            #pragma unroll
            for (int rr = 0; rr < 2; rr++) {
                const int rloc = rb + rr * 8;
                float av2 = sA[rloc];
                float h0 = fmaxf(fmaf(av2, d[rr * 2 + 0], bd0), 0.f);
                float h1 = fmaxf(fmaf(av2, d[rr * 2 + 1], bd1), 0.f);
                Aw0[rloc * 36 + c0 / 2] = pkh2(h0, h1);
            }
        }
    }
    cp_wait0();
    __syncthreads();   // h visible, up-B0 loaded

    // hoist up-phase A (h) fragments: invariant across all 16 N-chunks
    uint32_t afh[4][2][4];
    #pragma unroll
    for (int ks = 0; ks < 4; ks++) {
        ldsm_x4(aAddr0 + ks * 32, afh[ks][0]);
        ldsm_x4(aAddr0 + 16 * 144 + ks * 32, afh[ks][1]);
    }

    // ============ up phase: 16 N-chunks of 64, A = h (regs), B double-buffered ============
    #pragma unroll 1
    for (int nc = 0; nc < 16; nc++) {
        const uint32_t cur = (uint32_t)(nc & 1);
        if (nc < 15) {
            const __half* bs = g_wu + (nc + 1) * 4096 + bn0 * 64 + aq * 8;
            const uint32_t bo = (cur ^ 1u) * 9216u;
            #pragma unroll
            for (int j = 0; j < 2; j++)
                cpasync16(bdst + bo + (uint32_t)(j * 32) * 144, bs + j * 32 * 64);
            cp_commit();
        }
        #pragma unroll
        for (int i = 0; i < 8; i++)
            #pragma unroll
            for (int j = 0; j < 4; j++) acc[i][j] = 0.f;
        {
            const uint32_t bA = bAddr0 + cur * 9216u;
            #pragma unroll
            for (int ks = 0; ks < 4; ks++) {
                uint32_t bf[2][4];
                ldsm_x4(bA + ks * 32, bf[0]);
                ldsm_x4(bA + 16 * 144 + ks * 32, bf[1]);
                #pragma unroll
                for (int mt = 0; mt < 2; mt++)
                    #pragma unroll
                    for (int nt = 0; nt < 4; nt++) {
                        const int n2 = nt >> 1, s = (nt & 1) * 2;
                        mma_f16(acc[mt * 4 + nt], afh[ks][mt][0], afh[ks][mt][1],
                                afh[ks][mt][2], afh[ks][mt][3], bf[n2][s], bf[n2][s + 1]);
                    }
            }
        }
        // epilogue: out = acc + b_up
        const int nb64 = nc * 64;
        #pragma unroll
        for (int nt = 0; nt < 4; nt++) {
            const int c0 = warpN * 32 + nt * 8 + (lane & 3) * 2;
            const float u0 = __ldg(bup + nb64 + c0), u1 = __ldg(bup + nb64 + c0 + 1);
            #pragma unroll
            for (int mt = 0; mt < 2; mt++) {
                const float* d = acc[mt * 4 + nt];
                const int rb = warpM * 32 + mt * 16 + (lane >> 2);
                #pragma unroll
                for (int rr = 0; rr < 2; rr++) {
                    int row = row0 + rb + rr * 8;
                    if (row < ROWS_TOT) {
                        float2 v = make_float2(d[rr * 2 + 0] + u0, d[rr * 2 + 1] + u1);
                        *(float2*)(out + (size_t)row * 1024 + nb64 + c0) = v;
                    }
                }
            }
        }
        cp_wait0();
        __syncthreads();
    }
}

// ---------------- launch ----------------
extern "C" void kernel_launch(void* const* d_in, const int* in_sizes, int n_in,
                              void* d_out, int out_size) {
    (void)in_sizes; (void)n_in; (void)out_size;
    const float* x   = (const float*)d_in[0];
    const float* s_f = (const float*)d_in[1];
    const float* s_y = (const float*)d_in[2];
    const float* P   = (const float*)d_in[3];
    const float* Wd  = (const float*)d_in[4];
    const float* bd  = (const float*)d_in[5];
    const float* Wu  = (const float*)d_in[6];
    const float* bu  = (const float*)d_in[7];
    float* out = (float*)d_out;

    static bool attr_set = false;
    if (!attr_set) {
        cudaFuncSetAttribute(fused2_k, cudaFuncAttributeMaxDynamicSharedMemorySize, SM_BYTES);
        attr_set = true;
    }

    prep_all_k<<<672, 256>>>(Wd, Wu, s_f, s_y);
    select3_k<<<8, 256>>>(P);
    convert_k<<<5008, 256>>>(x, s_f);
    fused2_k<<<313, 256, SM_BYTES>>>(bd, bu, out);
}